// round 2
// baseline (speedup 1.0000x reference)
#include <cuda_runtime.h>

#define NPT 16384
#define BB  2

__device__ float g_f [BB*NPT*64];
__device__ float g_q [BB*NPT*64];
__device__ float g_kk[BB*NPT*64];
__device__ float g_vv[BB*NPT*64];

__device__ float g_W1f[32*64];
__device__ float g_t1[64];
__device__ float g_WqT[64*64], g_WkT[64*64], g_WvT[64*64];
__device__ float g_bqv[64], g_bkv[64], g_bvv[64];
__device__ float g_Wp1f[9], g_tp[3];
__device__ float g_Wp2b[64*4];
__device__ float g_s0t0[64*2];
__device__ float g_Ww1f[64*8];
__device__ float g_tw1[8], g_Ww2m[64], g_bw2v[8];
__device__ float g_smt[64*2];
__device__ float g_W2T[64*64], g_t2[64];

__global__ void k_prep(const float* __restrict__ W1,  const float* __restrict__ bn1,
                       const float* __restrict__ Wq,  const float* __restrict__ bq,
                       const float* __restrict__ Wk,  const float* __restrict__ bk,
                       const float* __restrict__ Wv,  const float* __restrict__ bv,
                       const float* __restrict__ Wp1, const float* __restrict__ bnp1,
                       const float* __restrict__ Wp2, const float* __restrict__ bp2,
                       const float* __restrict__ bnw0,const float* __restrict__ Ww1,
                       const float* __restrict__ bnw1,const float* __restrict__ Ww2,
                       const float* __restrict__ bw2, const float* __restrict__ bn_mid,
                       const float* __restrict__ W2,  const float* __restrict__ bn2)
{
    int t = threadIdx.x;
    if (t < 64) {
        int c = t;
        float s1 = bn1[c] * rsqrtf(bn1[192+c] + 1e-5f);
        g_t1[c] = bn1[64+c] - bn1[128+c]*s1;
        for (int i = 0; i < 32; i++) g_W1f[i*64+c] = W1[c*32+i]*s1;
        for (int i = 0; i < 64; i++) {
            g_WqT[i*64+c] = Wq[c*64+i];
            g_WkT[i*64+c] = Wk[c*64+i];
            g_WvT[i*64+c] = Wv[c*64+i];
        }
        g_bqv[c] = bq[c]; g_bkv[c] = bk[c]; g_bvv[c] = bv[c];
        g_Wp2b[c*4+0] = Wp2[c*3+0];
        g_Wp2b[c*4+1] = Wp2[c*3+1];
        g_Wp2b[c*4+2] = Wp2[c*3+2];
        g_Wp2b[c*4+3] = bp2[c];
        float s0 = bnw0[c] * rsqrtf(bnw0[192+c] + 1e-5f);
        g_s0t0[c*2+0] = s0;
        g_s0t0[c*2+1] = bnw0[64+c] - bnw0[128+c]*s0;
        float sm = bn_mid[c] * rsqrtf(bn_mid[192+c] + 1e-5f);
        g_smt[c*2+0] = sm;
        g_smt[c*2+1] = bn_mid[64+c] - bn_mid[128+c]*sm;
        float s2 = bn2[c] * rsqrtf(bn2[192+c] + 1e-5f);
        for (int i = 0; i < 64; i++) g_W2T[i*64+c] = W2[c*64+i]*s2;
        g_t2[c] = bn2[64+c] - bn2[128+c]*s2;
    }
    if (t < 3) {
        float sp = bnp1[t] * rsqrtf(bnp1[9+t] + 1e-5f);
        for (int cc = 0; cc < 3; cc++) g_Wp1f[t*3+cc] = Wp1[t*3+cc]*sp;
        g_tp[t] = bnp1[3+t] - bnp1[6+t]*sp;
    }
    if (t < 8) {
        int j = t;
        float sw = bnw1[j] * rsqrtf(bnw1[24+j] + 1e-5f);
        for (int c = 0; c < 64; c++) g_Ww1f[c*8+j] = Ww1[j*64+c]*sw;
        g_tw1[j] = bnw1[8+j] - bnw1[16+j]*sw;
        g_bw2v[j] = bw2[j];
        for (int i = 0; i < 8; i++) g_Ww2m[j*8+i] = Ww2[j*8+i];
    }
}

// f = relu(bn1(W1 x)); q/k/v projections; point-major stores.
__global__ void __launch_bounds__(256) k_feat(const float* __restrict__ feat)
{
    __shared__ float sfe[32*68];
    __shared__ float sf [64*68];
    int t  = threadIdx.x;
    int b  = blockIdx.y;
    int n0 = blockIdx.x * 64;

    #pragma unroll
    for (int r = 0; r < 8; r++) {
        int li = r*256 + t;
        int i = li >> 6, p = li & 63;
        sfe[i*68+p] = feat[(size_t)(b*32 + i)*NPT + n0 + p];
    }
    __syncthreads();

    int cc = t & 15, pg = t >> 4;
    int cb = 4*cc, pb = 4*pg;

    float af[4][4];
    #pragma unroll
    for (int a = 0; a < 4; a++)
        #pragma unroll
        for (int bj = 0; bj < 4; bj++) af[a][bj] = 0.f;

    #pragma unroll
    for (int i = 0; i < 32; i++) {
        float4 w  = *(const float4*)&g_W1f[i*64 + cb];
        float4 fv = *(const float4*)&sfe[i*68 + pb];
        float wc[4] = {w.x,w.y,w.z,w.w};
        float fp[4] = {fv.x,fv.y,fv.z,fv.w};
        #pragma unroll
        for (int ch = 0; ch < 4; ch++)
            #pragma unroll
            for (int pp = 0; pp < 4; pp++)
                af[ch][pp] = fmaf(wc[ch], fp[pp], af[ch][pp]);
    }
    {
        float4 t1v = *(const float4*)&g_t1[cb];
        float tb[4] = {t1v.x, t1v.y, t1v.z, t1v.w};
        #pragma unroll
        for (int ch = 0; ch < 4; ch++)
            #pragma unroll
            for (int pp = 0; pp < 4; pp++)
                af[ch][pp] = fmaxf(af[ch][pp] + tb[ch], 0.f);
    }
    #pragma unroll
    for (int ch = 0; ch < 4; ch++)
        *(float4*)&sf[(cb+ch)*68 + pb] = make_float4(af[ch][0], af[ch][1], af[ch][2], af[ch][3]);

    size_t fb = ((size_t)b*NPT + n0) * 64;
    #pragma unroll
    for (int pp = 0; pp < 4; pp++)
        *(float4*)&g_f[fb + (size_t)(pb+pp)*64 + cb] =
            make_float4(af[0][pp], af[1][pp], af[2][pp], af[3][pp]);
    __syncthreads();

    float aq[4][4], ak[4][4], av[4][4];
    #pragma unroll
    for (int a = 0; a < 4; a++)
        #pragma unroll
        for (int bj = 0; bj < 4; bj++) { aq[a][bj]=0.f; ak[a][bj]=0.f; av[a][bj]=0.f; }

    #pragma unroll 8
    for (int c = 0; c < 64; c++) {
        float4 fv = *(const float4*)&sf[c*68 + pb];
        float4 wq = *(const float4*)&g_WqT[c*64 + cb];
        float4 wk = *(const float4*)&g_WkT[c*64 + cb];
        float4 wv = *(const float4*)&g_WvT[c*64 + cb];
        float wcq[4] = {wq.x,wq.y,wq.z,wq.w};
        float wck[4] = {wk.x,wk.y,wk.z,wk.w};
        float wcv[4] = {wv.x,wv.y,wv.z,wv.w};
        float fp[4]  = {fv.x,fv.y,fv.z,fv.w};
        #pragma unroll
        for (int ch = 0; ch < 4; ch++)
            #pragma unroll
            for (int pp = 0; pp < 4; pp++) {
                aq[ch][pp] = fmaf(wcq[ch], fp[pp], aq[ch][pp]);
                ak[ch][pp] = fmaf(wck[ch], fp[pp], ak[ch][pp]);
                av[ch][pp] = fmaf(wcv[ch], fp[pp], av[ch][pp]);
            }
    }
    float4 bqv = *(const float4*)&g_bqv[cb];
    float4 bkv = *(const float4*)&g_bkv[cb];
    float4 bvv = *(const float4*)&g_bvv[cb];
    float bq_[4] = {bqv.x,bqv.y,bqv.z,bqv.w};
    float bk_[4] = {bkv.x,bkv.y,bkv.z,bkv.w};
    float bv_[4] = {bvv.x,bvv.y,bvv.z,bvv.w};
    #pragma unroll
    for (int pp = 0; pp < 4; pp++) {
        size_t off = fb + (size_t)(pb+pp)*64 + cb;
        *(float4*)&g_q [off] = make_float4(aq[0][pp]+bq_[0], aq[1][pp]+bq_[1],
                                           aq[2][pp]+bq_[2], aq[3][pp]+bq_[3]);
        *(float4*)&g_kk[off] = make_float4(ak[0][pp]+bk_[0], ak[1][pp]+bk_[1],
                                           ak[2][pp]+bk_[2], ak[3][pp]+bk_[3]);
        *(float4*)&g_vv[off] = make_float4(av[0][pp]+bv_[0], av[1][pp]+bv_[1],
                                           av[2][pp]+bv_[2], av[3][pp]+bv_[3]);
    }
}

__device__ __forceinline__ float lrelu(float x) { return fmaxf(x, 0.2f*x); }

// One warp per point. Lane l -> neighbor k = l&15, channel half h = l>>4.
__global__ void __launch_bounds__(256, 2) k_attn(const float* __restrict__ xyz,
                                                 const int*   __restrict__ nidx,
                                                 float*       __restrict__ out)
{
    __shared__ float swt[8][132];
    __shared__ float sxm[8][64];
    __shared__ float sout[512];

    int t = threadIdx.x;
    int warp = t >> 5, l = t & 31;
    int pid = blockIdx.x * 8 + warp;
    int b   = pid >> 14;
    int n   = pid & 16383;
    size_t rowb  = (size_t)b * NPT;
    size_t pbase = (rowb + n) * 64;

    int k = l & 15, h = l >> 4;
    int c0 = 32 * h;

    float P00=g_Wp1f[0], P01=g_Wp1f[1], P02=g_Wp1f[2];
    float P10=g_Wp1f[3], P11=g_Wp1f[4], P12=g_Wp1f[5];
    float P20=g_Wp1f[6], P21=g_Wp1f[7], P22=g_Wp1f[8];
    float tp0=g_tp[0], tp1=g_tp[1], tp2=g_tp[2];

    int idx = __ldg(nidx + (size_t)pid*16 + k);
    size_t gbase = (rowb + idx) * 64 + c0;
    const float* xr = xyz + (rowb + idx)*3;
    float X = __ldg(xr), Y = __ldg(xr+1), Z = __ldg(xr+2);
    float h0 = fmaxf(fmaf(P00, X, fmaf(P01, Y, fmaf(P02, Z, tp0))), 0.f);
    float h1 = fmaxf(fmaf(P10, X, fmaf(P11, Y, fmaf(P12, Z, tp1))), 0.f);
    float h2 = fmaxf(fmaf(P20, X, fmaf(P21, Y, fmaf(P22, Z, tp2))), 0.f);

    float xp[32];
    float w1p[8];
    #pragma unroll
    for (int j = 0; j < 8; j++) w1p[j] = 0.f;

    #pragma unroll
    for (int s = 0; s < 8; s++) {
        int cc = 4*s;
        int c  = c0 + cc;
        float4 kk = *(const float4*)(g_kk + gbase + cc);
        float4 vv = *(const float4*)(g_vv + gbase + cc);
        float4 qq = *(const float4*)(g_q  + pbase + c);
        float kr[4] = {kk.x,kk.y,kk.z,kk.w};
        float vr[4] = {vv.x,vv.y,vv.z,vv.w};
        float qr[4] = {qq.x,qq.y,qq.z,qq.w};
        #pragma unroll
        for (int e = 0; e < 4; e++) {
            int ch = c + e;
            float4 wp = *(const float4*)(g_Wp2b + ch*4);
            float pr = fmaf(wp.x, h0, fmaf(wp.y, h1, fmaf(wp.z, h2, wp.w)));
            xp[cc+e] = vr[e] + pr;
            float r  = kr[e] - qr[e] + pr;
            float2 st = *(const float2*)(g_s0t0 + ch*2);
            float u  = lrelu(fmaf(st.x, r, st.y));
            float4 wA = *(const float4*)(g_Ww1f + ch*8);
            float4 wB = *(const float4*)(g_Ww1f + ch*8 + 4);
            w1p[0] = fmaf(wA.x, u, w1p[0]); w1p[1] = fmaf(wA.y, u, w1p[1]);
            w1p[2] = fmaf(wA.z, u, w1p[2]); w1p[3] = fmaf(wA.w, u, w1p[3]);
            w1p[4] = fmaf(wB.x, u, w1p[4]); w1p[5] = fmaf(wB.y, u, w1p[5]);
            w1p[6] = fmaf(wB.z, u, w1p[6]); w1p[7] = fmaf(wB.w, u, w1p[7]);
        }
    }

    // combine the two channel halves
    #pragma unroll
    for (int j = 0; j < 8; j++)
        w1p[j] += __shfl_xor_sync(0xffffffffu, w1p[j], 16);

    float w1v[8];
    #pragma unroll
    for (int j = 0; j < 8; j++) w1v[j] = fmaxf(w1p[j] + __ldg(g_tw1 + j), 0.f);
    float wt[8];
    #pragma unroll
    for (int j = 0; j < 8; j++) {
        float a = __ldg(g_bw2v + j);
        #pragma unroll
        for (int i = 0; i < 8; i++) a = fmaf(__ldg(g_Ww2m + j*8 + i), w1v[i], a);
        wt[j] = a;
    }

    if (h == 0) {
        *(float4*)&swt[warp][k*8]   = make_float4(wt[0], wt[1], wt[2], wt[3]);
        *(float4*)&swt[warp][k*8+4] = make_float4(wt[4], wt[5], wt[6], wt[7]);
    }
    __syncwarp();

    // softmax over K: lane handles j = l>>2, k in [4*(l&3), +4)
    {
        int j = l >> 2, kq = l & 3;
        float v0 = swt[warp][(4*kq+0)*8 + j];
        float v1 = swt[warp][(4*kq+1)*8 + j];
        float v2 = swt[warp][(4*kq+2)*8 + j];
        float v3 = swt[warp][(4*kq+3)*8 + j];
        float mx = fmaxf(fmaxf(v0, v1), fmaxf(v2, v3));
        mx = fmaxf(mx, __shfl_xor_sync(0xffffffffu, mx, 1));
        mx = fmaxf(mx, __shfl_xor_sync(0xffffffffu, mx, 2));
        float e0 = __expf(v0 - mx), e1 = __expf(v1 - mx);
        float e2 = __expf(v2 - mx), e3 = __expf(v3 - mx);
        float sm = e0 + e1 + e2 + e3;
        sm += __shfl_xor_sync(0xffffffffu, sm, 1);
        sm += __shfl_xor_sync(0xffffffffu, sm, 2);
        float inv = __fdividef(1.f, sm);
        swt[warp][(4*kq+0)*8 + j] = e0 * inv;
        swt[warp][(4*kq+1)*8 + j] = e1 * inv;
        swt[warp][(4*kq+2)*8 + j] = e2 * inv;
        swt[warp][(4*kq+3)*8 + j] = e3 * inv;
    }
    __syncwarp();

    float4 wlo = *(const float4*)&swt[warp][k*8];
    float4 whi = *(const float4*)&swt[warp][k*8+4];
    float w8[8] = {wlo.x, wlo.y, wlo.z, wlo.w, whi.x, whi.y, whi.z, whi.w};

    float v[32];
    #pragma unroll
    for (int c = 0; c < 32; c++) v[c] = xp[c] * w8[c & 7];

    // value-splitting reduction over the 16 k-lanes: ends with channels 2l,2l+1
    {
        bool hi = (l & 8);
        #pragma unroll
        for (int j = 0; j < 16; j++) {
            float send = hi ? v[j] : v[j+16];
            float keep = hi ? v[j+16] : v[j];
            v[j] = keep + __shfl_xor_sync(0xffffffffu, send, 8);
        }
    }
    {
        bool hi = (l & 4);
        #pragma unroll
        for (int j = 0; j < 8; j++) {
            float send = hi ? v[j] : v[j+8];
            float keep = hi ? v[j+8] : v[j];
            v[j] = keep + __shfl_xor_sync(0xffffffffu, send, 4);
        }
    }
    {
        bool hi = (l & 2);
        #pragma unroll
        for (int j = 0; j < 4; j++) {
            float send = hi ? v[j] : v[j+4];
            float keep = hi ? v[j+4] : v[j];
            v[j] = keep + __shfl_xor_sync(0xffffffffu, send, 2);
        }
    }
    {
        bool hi = (l & 1);
        #pragma unroll
        for (int j = 0; j < 2; j++) {
            float send = hi ? v[j] : v[j+2];
            float keep = hi ? v[j+2] : v[j];
            v[j] = keep + __shfl_xor_sync(0xffffffffu, send, 1);
        }
    }

    // bn_mid + lrelu
    float4 sm4 = *(const float4*)(g_smt + 4*l);   // s(2l), t(2l), s(2l+1), t(2l+1)
    float xa = lrelu(fmaf(sm4.x, v[0], sm4.y));
    float xb = lrelu(fmaf(sm4.z, v[1], sm4.w));
    *(float2*)&sxm[warp][2*l] = make_float2(xa, xb);
    __syncwarp();

    // conv2 (BN folded) + residual + lrelu
    float2 t2v = *(const float2*)(g_t2 + 2*l);
    float o0 = t2v.x, o1 = t2v.y;
    #pragma unroll 4
    for (int c4 = 0; c4 < 64; c4 += 4) {
        float4 xv = *(const float4*)&sxm[warp][c4];
        float2 wa = *(const float2*)(g_W2T + (c4+0)*64 + 2*l);
        float2 wb = *(const float2*)(g_W2T + (c4+1)*64 + 2*l);
        float2 wc = *(const float2*)(g_W2T + (c4+2)*64 + 2*l);
        float2 wd = *(const float2*)(g_W2T + (c4+3)*64 + 2*l);
        o0 = fmaf(wa.x, xv.x, o0); o1 = fmaf(wa.y, xv.x, o1);
        o0 = fmaf(wb.x, xv.y, o0); o1 = fmaf(wb.y, xv.y, o1);
        o0 = fmaf(wc.x, xv.z, o0); o1 = fmaf(wc.y, xv.z, o1);
        o0 = fmaf(wd.x, xv.w, o0); o1 = fmaf(wd.y, xv.w, o1);
    }
    float2 fres = *(const float2*)(g_f + pbase + 2*l);
    o0 = lrelu(o0 + fres.x);
    o1 = lrelu(o1 + fres.y);
    sout[(2*l)*8 + warp]   = o0;
    sout[(2*l+1)*8 + warp] = o1;
    __syncthreads();

    // coalesced channel-major output
    int flat = t * 2;
    int c = flat >> 3, p = flat & 7;
    int bB = (blockIdx.x * 8) >> 14;
    int n0 = (blockIdx.x * 8) & 16383;
    float2 val = *(float2*)&sout[flat];
    *(float2*)&out[((size_t)(bB*64 + c))*NPT + n0 + p] = val;
}

extern "C" void kernel_launch(void* const* d_in, const int* in_sizes, int n_in,
                              void* d_out, int out_size)
{
    const float* feature = (const float*)d_in[0];
    const float* xyz     = (const float*)d_in[1];
    const float* W1      = (const float*)d_in[2];
    const float* bn1     = (const float*)d_in[3];
    const float* Wq      = (const float*)d_in[4];
    const float* bq      = (const float*)d_in[5];
    const float* Wk      = (const float*)d_in[6];
    const float* bk      = (const float*)d_in[7];
    const float* Wv      = (const float*)d_in[8];
    const float* bv      = (const float*)d_in[9];
    const float* Wp1     = (const float*)d_in[10];
    const float* bnp1    = (const float*)d_in[11];
    const float* Wp2     = (const float*)d_in[12];
    const float* bp2     = (const float*)d_in[13];
    const float* bnw0    = (const float*)d_in[14];
    const float* Ww1     = (const float*)d_in[15];
    const float* bnw1    = (const float*)d_in[16];
    const float* Ww2     = (const float*)d_in[17];
    const float* bw2     = (const float*)d_in[18];
    const float* bn_mid  = (const float*)d_in[19];
    const float* W2      = (const float*)d_in[20];
    const float* bn2     = (const float*)d_in[21];
    const int*   nidx    = (const int*)d_in[22];
    float* out = (float*)d_out;

    k_prep<<<1, 64>>>(W1, bn1, Wq, bq, Wk, bk, Wv, bv, Wp1, bnp1, Wp2, bp2,
                      bnw0, Ww1, bnw1, Ww2, bw2, bn_mid, W2, bn2);
    dim3 gf(NPT/64, BB);
    k_feat<<<gf, 256>>>(feature);
    k_attn<<<(BB*NPT)/8, 256>>>(xyz, nidx, out);
}

// round 4
// speedup vs baseline: 1.2489x; 1.2489x over previous
#include <cuda_runtime.h>

#define NPT 16384
#define BB  2

__device__ float g_f [BB*NPT*64];
__device__ float g_q [BB*NPT*64];
__device__ float g_kk[BB*NPT*64];
__device__ float g_vv[BB*NPT*64];

__device__ float g_W1f[32*64];
__device__ float g_t1[64];
__device__ float g_WqT[64*64], g_WkT[64*64], g_WvT[64*64];
__device__ float g_bqv[64], g_bkv[64], g_bvv[64];
__device__ float g_Wp1f[9], g_tp[3];
__device__ float g_Wp2b[64*4];
__device__ float g_s0t0[64*2];
__device__ float g_Ww1f[64*8];
__device__ float g_tw1[8], g_Ww2m[64], g_bw2v[8];
__device__ float g_smt[64*2];
__device__ float g_W2T[64*64], g_t2[64];

// ---------------- prep: 64 blocks x 64 threads ------------------------------
__global__ void k_prep(const float* __restrict__ W1,  const float* __restrict__ bn1,
                       const float* __restrict__ Wq,  const float* __restrict__ bq,
                       const float* __restrict__ Wk,  const float* __restrict__ bk,
                       const float* __restrict__ Wv,  const float* __restrict__ bv,
                       const float* __restrict__ Wp1, const float* __restrict__ bnp1,
                       const float* __restrict__ Wp2, const float* __restrict__ bp2,
                       const float* __restrict__ bnw0,const float* __restrict__ Ww1,
                       const float* __restrict__ bnw1,const float* __restrict__ Ww2,
                       const float* __restrict__ bw2, const float* __restrict__ bn_mid,
                       const float* __restrict__ W2,  const float* __restrict__ bn2)
{
    int c = blockIdx.x;   // 0..63 output channel
    int i = threadIdx.x;  // 0..63 input channel
    float s1 = bn1[c] * rsqrtf(bn1[192+c] + 1e-5f);
    float s2 = bn2[c] * rsqrtf(bn2[192+c] + 1e-5f);
    if (i < 32) g_W1f[i*64+c] = W1[c*32+i]*s1;
    g_WqT[i*64+c] = Wq[c*64+i];
    g_WkT[i*64+c] = Wk[c*64+i];
    g_WvT[i*64+c] = Wv[c*64+i];
    g_W2T[i*64+c] = W2[c*64+i]*s2;
    if (i < 8) {
        float sw = bnw1[i] * rsqrtf(bnw1[24+i] + 1e-5f);
        g_Ww1f[c*8+i] = Ww1[i*64+c]*sw;
    }
    if (i == 0) {
        g_t1[c] = bn1[64+c] - bn1[128+c]*s1;
        g_bqv[c] = bq[c]; g_bkv[c] = bk[c]; g_bvv[c] = bv[c];
        g_Wp2b[c*4+0] = Wp2[c*3+0];
        g_Wp2b[c*4+1] = Wp2[c*3+1];
        g_Wp2b[c*4+2] = Wp2[c*3+2];
        g_Wp2b[c*4+3] = bp2[c];
        float s0 = bnw0[c] * rsqrtf(bnw0[192+c] + 1e-5f);
        g_s0t0[c*2+0] = s0;
        g_s0t0[c*2+1] = bnw0[64+c] - bnw0[128+c]*s0;
        float sm = bn_mid[c] * rsqrtf(bn_mid[192+c] + 1e-5f);
        g_smt[c*2+0] = sm;
        g_smt[c*2+1] = bn_mid[64+c] - bn_mid[128+c]*sm;
        g_t2[c] = bn2[64+c] - bn2[128+c]*s2;
    }
    if (c == 0) {
        if (i < 3) {
            float sp = bnp1[i] * rsqrtf(bnp1[9+i] + 1e-5f);
            g_Wp1f[i*3+0] = Wp1[i*3+0]*sp;
            g_Wp1f[i*3+1] = Wp1[i*3+1]*sp;
            g_Wp1f[i*3+2] = Wp1[i*3+2]*sp;
            g_tp[i] = bnp1[3+i] - bnp1[6+i]*sp;
        }
        if (i < 8) {
            float sw = bnw1[i] * rsqrtf(bnw1[24+i] + 1e-5f);
            g_tw1[i]  = bnw1[8+i] - bnw1[16+i]*sw;
            g_bw2v[i] = bw2[i];
        }
        g_Ww2m[i] = Ww2[i];
    }
}

// ---------------- f = relu(bn1(W1 x)), point-major --------------------------
__global__ void __launch_bounds__(256) k_featf(const float* __restrict__ feat)
{
    __shared__ float sfe[32*68];
    int t  = threadIdx.x;
    int b  = blockIdx.y;
    int n0 = blockIdx.x * 64;

    #pragma unroll
    for (int r = 0; r < 8; r++) {
        int li = r*256 + t;
        int i = li >> 6, p = li & 63;
        sfe[i*68+p] = feat[(size_t)(b*32 + i)*NPT + n0 + p];
    }
    __syncthreads();

    int cc = t & 15, pg = t >> 4;
    int cb = 4*cc, pb = 4*pg;

    float af[4][4];
    #pragma unroll
    for (int a = 0; a < 4; a++)
        #pragma unroll
        for (int bj = 0; bj < 4; bj++) af[a][bj] = 0.f;

    #pragma unroll
    for (int i = 0; i < 32; i++) {
        float4 w  = *(const float4*)&g_W1f[i*64 + cb];
        float4 fv = *(const float4*)&sfe[i*68 + pb];
        float wc[4] = {w.x,w.y,w.z,w.w};
        float fp[4] = {fv.x,fv.y,fv.z,fv.w};
        #pragma unroll
        for (int ch = 0; ch < 4; ch++)
            #pragma unroll
            for (int pp = 0; pp < 4; pp++)
                af[ch][pp] = fmaf(wc[ch], fp[pp], af[ch][pp]);
    }
    float4 t1v = *(const float4*)&g_t1[cb];
    float tb[4] = {t1v.x, t1v.y, t1v.z, t1v.w};
    #pragma unroll
    for (int ch = 0; ch < 4; ch++)
        #pragma unroll
        for (int pp = 0; pp < 4; pp++)
            af[ch][pp] = fmaxf(af[ch][pp] + tb[ch], 0.f);

    size_t fb = ((size_t)b*NPT + n0) * 64;
    #pragma unroll
    for (int pp = 0; pp < 4; pp++)
        *(float4*)&g_f[fb + (size_t)(pb+pp)*64 + cb] =
            make_float4(af[0][pp], af[1][pp], af[2][pp], af[3][pp]);
}

// ---------------- q/k/v projection, one matrix per blockIdx.z ---------------
__global__ void __launch_bounds__(256) k_qkv()
{
    __shared__ float sf[64*68];
    int t  = threadIdx.x;
    int b  = blockIdx.y;
    int n0 = blockIdx.x * 64;
    int z  = blockIdx.z;
    const float* W    = (z == 0) ? g_WqT : (z == 1) ? g_WkT : g_WvT;
    const float* bias = (z == 0) ? g_bqv : (z == 1) ? g_bkv : g_bvv;
    float*       dst  = (z == 0) ? g_q   : (z == 1) ? g_kk  : g_vv;

    size_t fb = ((size_t)b*NPT + n0) * 64;

    // stage f tile transposed: sf[c][p], stride 68 (16B-aligned rows)
    int p = t & 63, chunk = t >> 6;
    #pragma unroll
    for (int j = 0; j < 4; j++) {
        int ch = chunk*16 + 4*j;
        float4 v = *(const float4*)&g_f[fb + (size_t)p*64 + ch];
        sf[(ch+0)*68+p] = v.x;
        sf[(ch+1)*68+p] = v.y;
        sf[(ch+2)*68+p] = v.z;
        sf[(ch+3)*68+p] = v.w;
    }
    __syncthreads();

    int cc = t & 15, pg = t >> 4;
    int cb = 4*cc, pb = 4*pg;

    float a[4][4];
    #pragma unroll
    for (int x = 0; x < 4; x++)
        #pragma unroll
        for (int y = 0; y < 4; y++) a[x][y] = 0.f;

    #pragma unroll 8
    for (int c = 0; c < 64; c++) {
        float4 w  = *(const float4*)&W[c*64 + cb];
        float4 fv = *(const float4*)&sf[c*68 + pb];
        float wc[4] = {w.x,w.y,w.z,w.w};
        float fp[4] = {fv.x,fv.y,fv.z,fv.w};
        #pragma unroll
        for (int ch = 0; ch < 4; ch++)
            #pragma unroll
            for (int pp = 0; pp < 4; pp++)
                a[ch][pp] = fmaf(wc[ch], fp[pp], a[ch][pp]);
    }
    float4 bb = *(const float4*)&bias[cb];
    float bvr[4] = {bb.x, bb.y, bb.z, bb.w};
    #pragma unroll
    for (int pp = 0; pp < 4; pp++)
        *(float4*)&dst[fb + (size_t)(pb+pp)*64 + cb] =
            make_float4(a[0][pp]+bvr[0], a[1][pp]+bvr[1], a[2][pp]+bvr[2], a[3][pp]+bvr[3]);
}

__device__ __forceinline__ float lrelu(float x) { return fmaxf(x, 0.2f*x); }

// ---------------- attention + aggregation + output --------------------------
// One warp per point. Lane l -> neighbor k = l&15, channel half h = l>>4.
__global__ void __launch_bounds__(256, 2) k_attn(const float* __restrict__ xyz,
                                                 const int*   __restrict__ nidx,
                                                 float*       __restrict__ out)
{
    __shared__ float swt[8][132];
    __shared__ float sxm[8][64];
    __shared__ float sout[512];
    __shared__ float sWp2b[256];
    __shared__ float sS0t0[128];
    __shared__ float sWw1f[512];
    __shared__ float sWw2[64];
    __shared__ float sAux[16];   // [0:8) tw1, [8:16) bw2

    int t = threadIdx.x;
    sWp2b[t]      = g_Wp2b[t];
    sWw1f[t]      = g_Ww1f[t];
    sWw1f[256+t]  = g_Ww1f[256+t];
    if (t < 128)  sS0t0[t] = g_s0t0[t];
    if (t < 64)   sWw2[t]  = g_Ww2m[t];
    if (t < 8)  { sAux[t] = g_tw1[t]; sAux[8+t] = g_bw2v[t]; }
    __syncthreads();

    int warp = t >> 5, l = t & 31;
    int pid = blockIdx.x * 8 + warp;
    int b   = pid >> 14;
    int n   = pid & 16383;
    size_t rowb  = (size_t)b * NPT;
    size_t pbase = (rowb + n) * 64;

    int k = l & 15, h = l >> 4;
    int c0 = 32 * h;

    float P00=g_Wp1f[0], P01=g_Wp1f[1], P02=g_Wp1f[2];
    float P10=g_Wp1f[3], P11=g_Wp1f[4], P12=g_Wp1f[5];
    float P20=g_Wp1f[6], P21=g_Wp1f[7], P22=g_Wp1f[8];
    float tp0=g_tp[0], tp1=g_tp[1], tp2=g_tp[2];

    int idx = __ldg(nidx + (size_t)pid*16 + k);
    size_t gbase = (rowb + idx) * 64 + c0;
    const float* xr = xyz + (rowb + idx)*3;
    float X = __ldg(xr), Y = __ldg(xr+1), Z = __ldg(xr+2);
    float h0 = fmaxf(fmaf(P00, X, fmaf(P01, Y, fmaf(P02, Z, tp0))), 0.f);
    float h1 = fmaxf(fmaf(P10, X, fmaf(P11, Y, fmaf(P12, Z, tp1))), 0.f);
    float h2 = fmaxf(fmaf(P20, X, fmaf(P21, Y, fmaf(P22, Z, tp2))), 0.f);

    float xp[32];
    float w1p[8];
    #pragma unroll
    for (int j = 0; j < 8; j++) w1p[j] = 0.f;

    #pragma unroll
    for (int s = 0; s < 8; s++) {
        int cc = 4*s;
        int c  = c0 + cc;
        float4 kk = *(const float4*)(g_kk + gbase + cc);
        float4 vv = *(const float4*)(g_vv + gbase + cc);
        float4 qq = *(const float4*)(g_q  + pbase + c);
        float kr[4] = {kk.x,kk.y,kk.z,kk.w};
        float vr[4] = {vv.x,vv.y,vv.z,vv.w};
        float qr[4] = {qq.x,qq.y,qq.z,qq.w};
        #pragma unroll
        for (int e = 0; e < 4; e++) {
            int ch = c + e;
            float4 wp = *(const float4*)(sWp2b + ch*4);
            float pr = fmaf(wp.x, h0, fmaf(wp.y, h1, fmaf(wp.z, h2, wp.w)));
            xp[cc+e] = vr[e] + pr;
            float r  = kr[e] - qr[e] + pr;
            float2 st = *(const float2*)(sS0t0 + ch*2);
            float u  = lrelu(fmaf(st.x, r, st.y));
            float4 wA = *(const float4*)(sWw1f + ch*8);
            float4 wB = *(const float4*)(sWw1f + ch*8 + 4);
            w1p[0] = fmaf(wA.x, u, w1p[0]); w1p[1] = fmaf(wA.y, u, w1p[1]);
            w1p[2] = fmaf(wA.z, u, w1p[2]); w1p[3] = fmaf(wA.w, u, w1p[3]);
            w1p[4] = fmaf(wB.x, u, w1p[4]); w1p[5] = fmaf(wB.y, u, w1p[5]);
            w1p[6] = fmaf(wB.z, u, w1p[6]); w1p[7] = fmaf(wB.w, u, w1p[7]);
        }
    }

    // combine the two channel halves (both sides get the full sum)
    #pragma unroll
    for (int j = 0; j < 8; j++)
        w1p[j] += __shfl_xor_sync(0xffffffffu, w1p[j], 16);

    float w1v[8];
    #pragma unroll
    for (int j = 0; j < 8; j++) w1v[j] = fmaxf(w1p[j] + sAux[j], 0.f);

    // each h-half computes 4 of the 8 outputs
    float wt[4];
    #pragma unroll
    for (int jj = 0; jj < 4; jj++) {
        int j = 4*h + jj;
        float a = sAux[8+j];
        #pragma unroll
        for (int i = 0; i < 8; i++) a = fmaf(sWw2[j*8+i], w1v[i], a);
        wt[jj] = a;
    }
    *(float4*)&swt[warp][k*8 + 4*h] = make_float4(wt[0], wt[1], wt[2], wt[3]);
    __syncwarp();

    // softmax over K: lane handles j = l>>2, k in [4*(l&3), +4)
    {
        int j = l >> 2, kq = l & 3;
        float v0 = swt[warp][(4*kq+0)*8 + j];
        float v1 = swt[warp][(4*kq+1)*8 + j];
        float v2 = swt[warp][(4*kq+2)*8 + j];
        float v3 = swt[warp][(4*kq+3)*8 + j];
        float mx = fmaxf(fmaxf(v0, v1), fmaxf(v2, v3));
        mx = fmaxf(mx, __shfl_xor_sync(0xffffffffu, mx, 1));
        mx = fmaxf(mx, __shfl_xor_sync(0xffffffffu, mx, 2));
        float e0 = __expf(v0 - mx), e1 = __expf(v1 - mx);
        float e2 = __expf(v2 - mx), e3 = __expf(v3 - mx);
        float sm = e0 + e1 + e2 + e3;
        sm += __shfl_xor_sync(0xffffffffu, sm, 1);
        sm += __shfl_xor_sync(0xffffffffu, sm, 2);
        float inv = __fdividef(1.f, sm);
        swt[warp][(4*kq+0)*8 + j] = e0 * inv;
        swt[warp][(4*kq+1)*8 + j] = e1 * inv;
        swt[warp][(4*kq+2)*8 + j] = e2 * inv;
        swt[warp][(4*kq+3)*8 + j] = e3 * inv;
    }
    __syncwarp();

    float4 wlo = *(const float4*)&swt[warp][k*8];
    float4 whi = *(const float4*)&swt[warp][k*8+4];
    float w8[8] = {wlo.x, wlo.y, wlo.z, wlo.w, whi.x, whi.y, whi.z, whi.w};

    float v[32];
    #pragma unroll
    for (int c = 0; c < 32; c++) v[c] = xp[c] * w8[c & 7];

    // value-splitting reduction over the 16 k-lanes -> channels 2l, 2l+1
    {
        bool hi = (l & 8);
        #pragma unroll
        for (int j = 0; j < 16; j++) {
            float send = hi ? v[j] : v[j+16];
            float keep = hi ? v[j+16] : v[j];
            v[j] = keep + __shfl_xor_sync(0xffffffffu, send, 8);
        }
    }
    {
        bool hi = (l & 4);
        #pragma unroll
        for (int j = 0; j < 8; j++) {
            float send = hi ? v[j] : v[j+8];
            float keep = hi ? v[j+8] : v[j];
            v[j] = keep + __shfl_xor_sync(0xffffffffu, send, 4);
        }
    }
    {
        bool hi = (l & 2);
        #pragma unroll
        for (int j = 0; j < 4; j++) {
            float send = hi ? v[j] : v[j+4];
            float keep = hi ? v[j+4] : v[j];
            v[j] = keep + __shfl_xor_sync(0xffffffffu, send, 2);
        }
    }
    {
        bool hi = (l & 1);
        #pragma unroll
        for (int j = 0; j < 2; j++) {
            float send = hi ? v[j] : v[j+2];
            float keep = hi ? v[j+2] : v[j];
            v[j] = keep + __shfl_xor_sync(0xffffffffu, send, 1);
        }
    }

    // bn_mid + lrelu
    float4 sm4 = *(const float4*)(g_smt + 4*l);
    float xa = lrelu(fmaf(sm4.x, v[0], sm4.y));
    float xb = lrelu(fmaf(sm4.z, v[1], sm4.w));
    *(float2*)&sxm[warp][2*l] = make_float2(xa, xb);
    __syncwarp();

    // conv2 (BN folded) + residual + lrelu
    float2 t2v = *(const float2*)(g_t2 + 2*l);
    float o0 = t2v.x, o1 = t2v.y;
    #pragma unroll 4
    for (int c4 = 0; c4 < 64; c4 += 4) {
        float4 xv = *(const float4*)&sxm[warp][c4];
        float2 wa = *(const float2*)(g_W2T + (c4+0)*64 + 2*l);
        float2 wb = *(const float2*)(g_W2T + (c4+1)*64 + 2*l);
        float2 wc = *(const float2*)(g_W2T + (c4+2)*64 + 2*l);
        float2 wd = *(const float2*)(g_W2T + (c4+3)*64 + 2*l);
        o0 = fmaf(wa.x, xv.x, o0); o1 = fmaf(wa.y, xv.x, o1);
        o0 = fmaf(wb.x, xv.y, o0); o1 = fmaf(wb.y, xv.y, o1);
        o0 = fmaf(wc.x, xv.z, o0); o1 = fmaf(wc.y, xv.z, o1);
        o0 = fmaf(wd.x, xv.w, o0); o1 = fmaf(wd.y, xv.w, o1);
    }
    float2 fres = *(const float2*)(g_f + pbase + 2*l);
    o0 = lrelu(o0 + fres.x);
    o1 = lrelu(o1 + fres.y);
    sout[(2*l)*8 + warp]   = o0;
    sout[(2*l+1)*8 + warp] = o1;
    __syncthreads();

    // coalesced channel-major output
    int flat = t * 2;
    int c = flat >> 3, p = flat & 7;
    int bB = (blockIdx.x * 8) >> 14;
    int n0 = (blockIdx.x * 8) & 16383;
    float2 val = *(float2*)&sout[flat];
    *(float2*)&out[((size_t)(bB*64 + c))*NPT + n0 + p] = val;
}

extern "C" void kernel_launch(void* const* d_in, const int* in_sizes, int n_in,
                              void* d_out, int out_size)
{
    const float* feature = (const float*)d_in[0];
    const float* xyz     = (const float*)d_in[1];
    const float* W1      = (const float*)d_in[2];
    const float* bn1     = (const float*)d_in[3];
    const float* Wq      = (const float*)d_in[4];
    const float* bq      = (const float*)d_in[5];
    const float* Wk      = (const float*)d_in[6];
    const float* bk      = (const float*)d_in[7];
    const float* Wv      = (const float*)d_in[8];
    const float* bv      = (const float*)d_in[9];
    const float* Wp1     = (const float*)d_in[10];
    const float* bnp1    = (const float*)d_in[11];
    const float* Wp2     = (const float*)d_in[12];
    const float* bp2     = (const float*)d_in[13];
    const float* bnw0    = (const float*)d_in[14];
    const float* Ww1     = (const float*)d_in[15];
    const float* bnw1    = (const float*)d_in[16];
    const float* Ww2     = (const float*)d_in[17];
    const float* bw2     = (const float*)d_in[18];
    const float* bn_mid  = (const float*)d_in[19];
    const float* W2      = (const float*)d_in[20];
    const float* bn2     = (const float*)d_in[21];
    const int*   nidx    = (const int*)d_in[22];
    float* out = (float*)d_out;

    k_prep<<<64, 64>>>(W1, bn1, Wq, bq, Wk, bk, Wv, bv, Wp1, bnp1, Wp2, bp2,
                       bnw0, Ww1, bnw1, Ww2, bw2, bn_mid, W2, bn2);
    dim3 gf(NPT/64, BB);
    k_featf<<<gf, 256>>>(feature);
    dim3 gq(NPT/64, BB, 3);
    k_qkv<<<gq, 256>>>();
    k_attn<<<(BB*NPT)/8, 256>>>(xyz, nidx, out);
}

// round 5
// speedup vs baseline: 1.5031x; 1.2035x over previous
#include <cuda_runtime.h>

#define NPT 16384
#define BB  2

__device__ float g_f [BB*NPT*64];
__device__ float g_q [BB*NPT*64];
__device__ float g_kv[BB*NPT*128];   // [row][0:64]=k, [64:128]=v

__device__ float g_W1f[32*64];
__device__ float g_t1[64];
__device__ float g_WqT[64*64], g_WkT[64*64], g_WvT[64*64];
__device__ float g_bqv[64], g_bkv[64], g_bvv[64];
__device__ float g_Wp1f[9], g_tp[3];
__device__ float g_Wp2b[64*4];
__device__ float g_s0t0[64*2];
__device__ float g_Ww1f[64*8];
__device__ float g_tw1[8], g_Ww2m[64], g_bw2v[8];
__device__ float g_smt[64*2];
__device__ float g_W2T[64*64], g_t2[64];

// ---------------- prep: 64 blocks x 64 threads ------------------------------
__global__ void k_prep(const float* __restrict__ W1,  const float* __restrict__ bn1,
                       const float* __restrict__ Wq,  const float* __restrict__ bq,
                       const float* __restrict__ Wk,  const float* __restrict__ bk,
                       const float* __restrict__ Wv,  const float* __restrict__ bv,
                       const float* __restrict__ Wp1, const float* __restrict__ bnp1,
                       const float* __restrict__ Wp2, const float* __restrict__ bp2,
                       const float* __restrict__ bnw0,const float* __restrict__ Ww1,
                       const float* __restrict__ bnw1,const float* __restrict__ Ww2,
                       const float* __restrict__ bw2, const float* __restrict__ bn_mid,
                       const float* __restrict__ W2,  const float* __restrict__ bn2)
{
    int c = blockIdx.x;   // 0..63 output channel
    int i = threadIdx.x;  // 0..63 input channel
    float s1 = bn1[c] * rsqrtf(bn1[192+c] + 1e-5f);
    float s2 = bn2[c] * rsqrtf(bn2[192+c] + 1e-5f);
    if (i < 32) g_W1f[i*64+c] = W1[c*32+i]*s1;
    g_WqT[i*64+c] = Wq[c*64+i];
    g_WkT[i*64+c] = Wk[c*64+i];
    g_WvT[i*64+c] = Wv[c*64+i];
    g_W2T[i*64+c] = W2[c*64+i]*s2;
    if (i < 8) {
        float sw = bnw1[i] * rsqrtf(bnw1[24+i] + 1e-5f);
        g_Ww1f[c*8+i] = Ww1[i*64+c]*sw;
    }
    if (i == 0) {
        g_t1[c] = bn1[64+c] - bn1[128+c]*s1;
        g_bqv[c] = bq[c]; g_bkv[c] = bk[c]; g_bvv[c] = bv[c];
        g_Wp2b[c*4+0] = Wp2[c*3+0];
        g_Wp2b[c*4+1] = Wp2[c*3+1];
        g_Wp2b[c*4+2] = Wp2[c*3+2];
        g_Wp2b[c*4+3] = bp2[c];
        float s0 = bnw0[c] * rsqrtf(bnw0[192+c] + 1e-5f);
        g_s0t0[c*2+0] = s0;
        g_s0t0[c*2+1] = bnw0[64+c] - bnw0[128+c]*s0;
        float sm = bn_mid[c] * rsqrtf(bn_mid[192+c] + 1e-5f);
        g_smt[c*2+0] = sm;
        g_smt[c*2+1] = bn_mid[64+c] - bn_mid[128+c]*sm;
        g_t2[c] = bn2[64+c] - bn2[128+c]*s2;
    }
    if (c == 0) {
        if (i < 3) {
            float sp = bnp1[i] * rsqrtf(bnp1[9+i] + 1e-5f);
            g_Wp1f[i*3+0] = Wp1[i*3+0]*sp;
            g_Wp1f[i*3+1] = Wp1[i*3+1]*sp;
            g_Wp1f[i*3+2] = Wp1[i*3+2]*sp;
            g_tp[i] = bnp1[3+i] - bnp1[6+i]*sp;
        }
        if (i < 8) {
            float sw = bnw1[i] * rsqrtf(bnw1[24+i] + 1e-5f);
            g_tw1[i]  = bnw1[8+i] - bnw1[16+i]*sw;
            g_bw2v[i] = bw2[i];
        }
        g_Ww2m[i] = Ww2[i];
    }
}

// ---------------- f = relu(bn1(W1 x)), point-major --------------------------
__global__ void __launch_bounds__(256) k_featf(const float* __restrict__ feat)
{
    __shared__ float sfe[32*68];
    int t  = threadIdx.x;
    int b  = blockIdx.y;
    int n0 = blockIdx.x * 64;

    #pragma unroll
    for (int r = 0; r < 8; r++) {
        int li = r*256 + t;
        int i = li >> 6, p = li & 63;
        sfe[i*68+p] = feat[(size_t)(b*32 + i)*NPT + n0 + p];
    }
    __syncthreads();

    int cc = t & 15, pg = t >> 4;
    int cb = 4*cc, pb = 4*pg;

    float af[4][4];
    #pragma unroll
    for (int a = 0; a < 4; a++)
        #pragma unroll
        for (int bj = 0; bj < 4; bj++) af[a][bj] = 0.f;

    #pragma unroll
    for (int i = 0; i < 32; i++) {
        float4 w  = *(const float4*)&g_W1f[i*64 + cb];
        float4 fv = *(const float4*)&sfe[i*68 + pb];
        float wc[4] = {w.x,w.y,w.z,w.w};
        float fp[4] = {fv.x,fv.y,fv.z,fv.w};
        #pragma unroll
        for (int ch = 0; ch < 4; ch++)
            #pragma unroll
            for (int pp = 0; pp < 4; pp++)
                af[ch][pp] = fmaf(wc[ch], fp[pp], af[ch][pp]);
    }
    float4 t1v = *(const float4*)&g_t1[cb];
    float tb[4] = {t1v.x, t1v.y, t1v.z, t1v.w};
    #pragma unroll
    for (int ch = 0; ch < 4; ch++)
        #pragma unroll
        for (int pp = 0; pp < 4; pp++)
            af[ch][pp] = fmaxf(af[ch][pp] + tb[ch], 0.f);

    size_t fb = ((size_t)b*NPT + n0) * 64;
    #pragma unroll
    for (int pp = 0; pp < 4; pp++)
        *(float4*)&g_f[fb + (size_t)(pb+pp)*64 + cb] =
            make_float4(af[0][pp], af[1][pp], af[2][pp], af[3][pp]);
}

// ---------------- q/k/v projection, one matrix per blockIdx.z ---------------
// z=0 -> q (row stride 64), z=1 -> k half of g_kv, z=2 -> v half (stride 128)
__global__ void __launch_bounds__(256) k_qkv()
{
    __shared__ float sf[64*68];
    int t  = threadIdx.x;
    int b  = blockIdx.y;
    int n0 = blockIdx.x * 64;
    int z  = blockIdx.z;
    const float* W    = (z == 0) ? g_WqT : (z == 1) ? g_WkT : g_WvT;
    const float* bias = (z == 0) ? g_bqv : (z == 1) ? g_bkv : g_bvv;
    float*       dst  = (z == 0) ? g_q   : (z == 1) ? g_kv  : (g_kv + 64);
    int          dstr = (z == 0) ? 64 : 128;

    size_t fb = ((size_t)b*NPT + n0) * 64;

    // stage f tile transposed: sf[c][p], stride 68 (16B-aligned rows)
    int p = t & 63, chunk = t >> 6;
    #pragma unroll
    for (int j = 0; j < 4; j++) {
        int ch = chunk*16 + 4*j;
        float4 v = *(const float4*)&g_f[fb + (size_t)p*64 + ch];
        sf[(ch+0)*68+p] = v.x;
        sf[(ch+1)*68+p] = v.y;
        sf[(ch+2)*68+p] = v.z;
        sf[(ch+3)*68+p] = v.w;
    }
    __syncthreads();

    int cc = t & 15, pg = t >> 4;
    int cb = 4*cc, pb = 4*pg;

    float a[4][4];
    #pragma unroll
    for (int x = 0; x < 4; x++)
        #pragma unroll
        for (int y = 0; y < 4; y++) a[x][y] = 0.f;

    #pragma unroll 8
    for (int c = 0; c < 64; c++) {
        float4 w  = *(const float4*)&W[c*64 + cb];
        float4 fv = *(const float4*)&sf[c*68 + pb];
        float wc[4] = {w.x,w.y,w.z,w.w};
        float fp[4] = {fv.x,fv.y,fv.z,fv.w};
        #pragma unroll
        for (int ch = 0; ch < 4; ch++)
            #pragma unroll
            for (int pp = 0; pp < 4; pp++)
                a[ch][pp] = fmaf(wc[ch], fp[pp], a[ch][pp]);
    }
    float4 bb = *(const float4*)&bias[cb];
    float bvr[4] = {bb.x, bb.y, bb.z, bb.w};
    #pragma unroll
    for (int pp = 0; pp < 4; pp++)
        *(float4*)&dst[((size_t)b*NPT + n0 + pb + pp)*dstr + cb] =
            make_float4(a[0][pp]+bvr[0], a[1][pp]+bvr[1], a[2][pp]+bvr[2], a[3][pp]+bvr[3]);
}

__device__ __forceinline__ float lrelu(float x) { return fmaxf(x, 0.2f*x); }

// ---------------- attention + aggregation + output --------------------------
// One warp per point, 4 warps/block. Lane l -> neighbor k = l&15, half h = l>>4.
// k/v rows gathered cooperatively into shared with XOR-chunk swizzle.
#define WPB 4
__global__ void __launch_bounds__(128) k_attn(const float* __restrict__ xyz,
                                              const int*   __restrict__ nidx,
                                              float*       __restrict__ out)
{
    __shared__ float skv[WPB][16*128];  // 32 KB: per-warp 16 rows x 512B, swizzled
    __shared__ float swt[WPB][132];
    __shared__ float sxm[WPB][64];
    __shared__ float sout[WPB*64];
    __shared__ float sWp2b[256];
    __shared__ float sS0t0[128];
    __shared__ float sWw1f[512];
    __shared__ float sWw2[64];
    __shared__ float sAux[16];   // [0:8) tw1, [8:16) bw2

    int t = threadIdx.x;
    sWp2b[t]       = g_Wp2b[t];
    sWp2b[128+t]   = g_Wp2b[128+t];
    sWw1f[t]       = g_Ww1f[t];
    sWw1f[128+t]   = g_Ww1f[128+t];
    sWw1f[256+t]   = g_Ww1f[256+t];
    sWw1f[384+t]   = g_Ww1f[384+t];
    sS0t0[t]       = g_s0t0[t];
    if (t < 64)    sWw2[t] = g_Ww2m[t];
    if (t < 8)   { sAux[t] = g_tw1[t]; sAux[8+t] = g_bw2v[t]; }
    __syncthreads();

    int warp = t >> 5, l = t & 31;
    int pid = blockIdx.x * WPB + warp;
    int b   = pid >> 14;
    int n   = pid & 16383;
    size_t rowb  = (size_t)b * NPT;
    size_t pbase = (rowb + n) * 64;

    int k = l & 15, h = l >> 4;
    int c0 = 32 * h;

    const int* nrow = nidx + (size_t)pid*16;
    int myidx = (l < 16) ? __ldg(nrow + l) : 0;

    // cooperative gather: one full 512B k|v row per instruction, swizzled STS
    float* skvw = skv[warp];
    #pragma unroll
    for (int i = 0; i < 16; i++) {
        int r = __shfl_sync(0xffffffffu, myidx, i);
        const float4* src = (const float4*)(g_kv + (rowb + r)*128);
        float4 val = __ldg(src + l);
        int p = l ^ (i & 7);
        *(float4*)&skvw[i*128 + p*4] = val;
    }
    __syncwarp();

    // pos-MLP hidden for own neighbor k
    float P00=g_Wp1f[0], P01=g_Wp1f[1], P02=g_Wp1f[2];
    float P10=g_Wp1f[3], P11=g_Wp1f[4], P12=g_Wp1f[5];
    float P20=g_Wp1f[6], P21=g_Wp1f[7], P22=g_Wp1f[8];
    float tp0=g_tp[0], tp1=g_tp[1], tp2=g_tp[2];

    int idxk = __shfl_sync(0xffffffffu, myidx, k);
    const float* xr = xyz + (rowb + idxk)*3;
    float X = __ldg(xr), Y = __ldg(xr+1), Z = __ldg(xr+2);
    float h0 = fmaxf(fmaf(P00, X, fmaf(P01, Y, fmaf(P02, Z, tp0))), 0.f);
    float h1 = fmaxf(fmaf(P10, X, fmaf(P11, Y, fmaf(P12, Z, tp1))), 0.f);
    float h2 = fmaxf(fmaf(P20, X, fmaf(P21, Y, fmaf(P22, Z, tp2))), 0.f);

    float xp[32];
    float w1p[8];
    #pragma unroll
    for (int j = 0; j < 8; j++) w1p[j] = 0.f;

    int sw8 = k & 7;
    #pragma unroll
    for (int s = 0; s < 8; s++) {
        int cc = 4*s;
        int c  = c0 + cc;
        float4 kk = *(const float4*)&skvw[k*128 + ((h*8 + s)      ^ sw8)*4];
        float4 vv = *(const float4*)&skvw[k*128 + ((16 + h*8 + s) ^ sw8)*4];
        float4 qq = *(const float4*)(g_q + pbase + c);
        float kr[4] = {kk.x,kk.y,kk.z,kk.w};
        float vr[4] = {vv.x,vv.y,vv.z,vv.w};
        float qr[4] = {qq.x,qq.y,qq.z,qq.w};
        #pragma unroll
        for (int e = 0; e < 4; e++) {
            int ch = c + e;
            float4 wp = *(const float4*)(sWp2b + ch*4);
            float pr = fmaf(wp.x, h0, fmaf(wp.y, h1, fmaf(wp.z, h2, wp.w)));
            xp[cc+e] = vr[e] + pr;
            float r  = kr[e] - qr[e] + pr;
            float2 st = *(const float2*)(sS0t0 + ch*2);
            float u  = lrelu(fmaf(st.x, r, st.y));
            float4 wA = *(const float4*)(sWw1f + ch*8);
            float4 wB = *(const float4*)(sWw1f + ch*8 + 4);
            w1p[0] = fmaf(wA.x, u, w1p[0]); w1p[1] = fmaf(wA.y, u, w1p[1]);
            w1p[2] = fmaf(wA.z, u, w1p[2]); w1p[3] = fmaf(wA.w, u, w1p[3]);
            w1p[4] = fmaf(wB.x, u, w1p[4]); w1p[5] = fmaf(wB.y, u, w1p[5]);
            w1p[6] = fmaf(wB.z, u, w1p[6]); w1p[7] = fmaf(wB.w, u, w1p[7]);
        }
    }

    // combine the two channel halves
    #pragma unroll
    for (int j = 0; j < 8; j++)
        w1p[j] += __shfl_xor_sync(0xffffffffu, w1p[j], 16);

    float w1v[8];
    #pragma unroll
    for (int j = 0; j < 8; j++) w1v[j] = fmaxf(w1p[j] + sAux[j], 0.f);

    // each h-half computes 4 of the 8 Ww2 outputs
    float wt[4];
    #pragma unroll
    for (int jj = 0; jj < 4; jj++) {
        int j = 4*h + jj;
        float a = sAux[8+j];
        #pragma unroll
        for (int i = 0; i < 8; i++) a = fmaf(sWw2[j*8+i], w1v[i], a);
        wt[jj] = a;
    }
    *(float4*)&swt[warp][k*8 + 4*h] = make_float4(wt[0], wt[1], wt[2], wt[3]);
    __syncwarp();

    // softmax over K: lane handles j = l>>2, k in [4*(l&3), +4)
    {
        int j = l >> 2, kq = l & 3;
        float v0 = swt[warp][(4*kq+0)*8 + j];
        float v1 = swt[warp][(4*kq+1)*8 + j];
        float v2 = swt[warp][(4*kq+2)*8 + j];
        float v3 = swt[warp][(4*kq+3)*8 + j];
        float mx = fmaxf(fmaxf(v0, v1), fmaxf(v2, v3));
        mx = fmaxf(mx, __shfl_xor_sync(0xffffffffu, mx, 1));
        mx = fmaxf(mx, __shfl_xor_sync(0xffffffffu, mx, 2));
        float e0 = __expf(v0 - mx), e1 = __expf(v1 - mx);
        float e2 = __expf(v2 - mx), e3 = __expf(v3 - mx);
        float sm = e0 + e1 + e2 + e3;
        sm += __shfl_xor_sync(0xffffffffu, sm, 1);
        sm += __shfl_xor_sync(0xffffffffu, sm, 2);
        float inv = __fdividef(1.f, sm);
        swt[warp][(4*kq+0)*8 + j] = e0 * inv;
        swt[warp][(4*kq+1)*8 + j] = e1 * inv;
        swt[warp][(4*kq+2)*8 + j] = e2 * inv;
        swt[warp][(4*kq+3)*8 + j] = e3 * inv;
    }
    __syncwarp();

    float4 wlo = *(const float4*)&swt[warp][k*8];
    float4 whi = *(const float4*)&swt[warp][k*8+4];
    float w8[8] = {wlo.x, wlo.y, wlo.z, wlo.w, whi.x, whi.y, whi.z, whi.w};

    float v[32];
    #pragma unroll
    for (int c = 0; c < 32; c++) v[c] = xp[c] * w8[c & 7];

    // value-splitting reduction over the 16 k-lanes -> channels 2l, 2l+1
    {
        bool hi = (l & 8);
        #pragma unroll
        for (int j = 0; j < 16; j++) {
            float send = hi ? v[j] : v[j+16];
            float keep = hi ? v[j+16] : v[j];
            v[j] = keep + __shfl_xor_sync(0xffffffffu, send, 8);
        }
    }
    {
        bool hi = (l & 4);
        #pragma unroll
        for (int j = 0; j < 8; j++) {
            float send = hi ? v[j] : v[j+8];
            float keep = hi ? v[j+8] : v[j];
            v[j] = keep + __shfl_xor_sync(0xffffffffu, send, 4);
        }
    }
    {
        bool hi = (l & 2);
        #pragma unroll
        for (int j = 0; j < 4; j++) {
            float send = hi ? v[j] : v[j+4];
            float keep = hi ? v[j+4] : v[j];
            v[j] = keep + __shfl_xor_sync(0xffffffffu, send, 2);
        }
    }
    {
        bool hi = (l & 1);
        #pragma unroll
        for (int j = 0; j < 2; j++) {
            float send = hi ? v[j] : v[j+2];
            float keep = hi ? v[j+2] : v[j];
            v[j] = keep + __shfl_xor_sync(0xffffffffu, send, 1);
        }
    }

    // bn_mid + lrelu
    float4 sm4 = *(const float4*)(g_smt + 4*l);
    float xa = lrelu(fmaf(sm4.x, v[0], sm4.y));
    float xb = lrelu(fmaf(sm4.z, v[1], sm4.w));
    *(float2*)&sxm[warp][2*l] = make_float2(xa, xb);
    __syncwarp();

    // conv2 (BN folded) + residual + lrelu
    float2 t2v = *(const float2*)(g_t2 + 2*l);
    float o0 = t2v.x, o1 = t2v.y;
    #pragma unroll 4
    for (int c4 = 0; c4 < 64; c4 += 4) {
        float4 xv = *(const float4*)&sxm[warp][c4];
        float2 wa = *(const float2*)(g_W2T + (c4+0)*64 + 2*l);
        float2 wb = *(const float2*)(g_W2T + (c4+1)*64 + 2*l);
        float2 wc = *(const float2*)(g_W2T + (c4+2)*64 + 2*l);
        float2 wd = *(const float2*)(g_W2T + (c4+3)*64 + 2*l);
        o0 = fmaf(wa.x, xv.x, o0); o1 = fmaf(wa.y, xv.x, o1);
        o0 = fmaf(wb.x, xv.y, o0); o1 = fmaf(wb.y, xv.y, o1);
        o0 = fmaf(wc.x, xv.z, o0); o1 = fmaf(wc.y, xv.z, o1);
        o0 = fmaf(wd.x, xv.w, o0); o1 = fmaf(wd.y, xv.w, o1);
    }
    float2 fres = *(const float2*)(g_f + pbase + 2*l);
    o0 = lrelu(o0 + fres.x);
    o1 = lrelu(o1 + fres.y);
    sout[(2*l)*WPB + warp]   = o0;
    sout[(2*l+1)*WPB + warp] = o1;
    __syncthreads();

    // coalesced channel-major output (WPB=4 points per block, aligned in n)
    int flat = t * 2;
    int c = flat >> 2, p = flat & 3;
    int bB = (blockIdx.x * WPB) >> 14;
    int n0 = (blockIdx.x * WPB) & 16383;
    float2 val = *(float2*)&sout[flat];
    *(float2*)&out[((size_t)(bB*64 + c))*NPT + n0 + p] = val;
}

extern "C" void kernel_launch(void* const* d_in, const int* in_sizes, int n_in,
                              void* d_out, int out_size)
{
    const float* feature = (const float*)d_in[0];
    const float* xyz     = (const float*)d_in[1];
    const float* W1      = (const float*)d_in[2];
    const float* bn1     = (const float*)d_in[3];
    const float* Wq      = (const float*)d_in[4];
    const float* bq      = (const float*)d_in[5];
    const float* Wk      = (const float*)d_in[6];
    const float* bk      = (const float*)d_in[7];
    const float* Wv      = (const float*)d_in[8];
    const float* bv      = (const float*)d_in[9];
    const float* Wp1     = (const float*)d_in[10];
    const float* bnp1    = (const float*)d_in[11];
    const float* Wp2     = (const float*)d_in[12];
    const float* bp2     = (const float*)d_in[13];
    const float* bnw0    = (const float*)d_in[14];
    const float* Ww1     = (const float*)d_in[15];
    const float* bnw1    = (const float*)d_in[16];
    const float* Ww2     = (const float*)d_in[17];
    const float* bw2     = (const float*)d_in[18];
    const float* bn_mid  = (const float*)d_in[19];
    const float* W2      = (const float*)d_in[20];
    const float* bn2     = (const float*)d_in[21];
    const int*   nidx    = (const int*)d_in[22];
    float* out = (float*)d_out;

    k_prep<<<64, 64>>>(W1, bn1, Wq, bq, Wk, bk, Wv, bv, Wp1, bnp1, Wp2, bp2,
                       bnw0, Ww1, bnw1, Ww2, bw2, bn_mid, W2, bn2);
    dim3 gf(NPT/64, BB);
    k_featf<<<gf, 256>>>(feature);
    dim3 gq(NPT/64, BB, 3);
    k_qkv<<<gq, 256>>>();
    k_attn<<<(BB*NPT)/WPB, 128>>>(xyz, nidx, out);
}

// round 6
// speedup vs baseline: 1.7031x; 1.1331x over previous
#include <cuda_runtime.h>

#define NPT 16384
#define BB  2

__device__ float g_f [BB*NPT*64];
__device__ float g_q [BB*NPT*64];     // QS = s0*q - t0
__device__ float g_kv[BB*NPT*128];    // [row][0:64]=s0*(k+pr), [64:128]=v+pr

__device__ float g_W1f[32*64];
__device__ float g_t1[64];
__device__ float g_WqT[64*64], g_WkT[64*64], g_WvT[64*64];
__device__ float g_bqv[64], g_bkv[64], g_bvv[64];
__device__ float g_Wp1f[9], g_tp[3];
__device__ float g_Wp2b[64*4];
__device__ float g_s0t0[64*2];
__device__ float g_Ww1f[64*8];
__device__ float g_tw1[8], g_Ww2m[64], g_bw2v[8];
__device__ float g_smt[64*2];
__device__ float g_W2T[64*64], g_t2[64];

// ---------------- prep: 64 blocks x 64 threads ------------------------------
__global__ void k_prep(const float* __restrict__ W1,  const float* __restrict__ bn1,
                       const float* __restrict__ Wq,  const float* __restrict__ bq,
                       const float* __restrict__ Wk,  const float* __restrict__ bk,
                       const float* __restrict__ Wv,  const float* __restrict__ bv,
                       const float* __restrict__ Wp1, const float* __restrict__ bnp1,
                       const float* __restrict__ Wp2, const float* __restrict__ bp2,
                       const float* __restrict__ bnw0,const float* __restrict__ Ww1,
                       const float* __restrict__ bnw1,const float* __restrict__ Ww2,
                       const float* __restrict__ bw2, const float* __restrict__ bn_mid,
                       const float* __restrict__ W2,  const float* __restrict__ bn2)
{
    int c = blockIdx.x;   // 0..63 output channel
    int i = threadIdx.x;  // 0..63 input channel
    float s1 = bn1[c] * rsqrtf(bn1[192+c] + 1e-5f);
    float s2 = bn2[c] * rsqrtf(bn2[192+c] + 1e-5f);
    if (i < 32) g_W1f[i*64+c] = W1[c*32+i]*s1;
    g_WqT[i*64+c] = Wq[c*64+i];
    g_WkT[i*64+c] = Wk[c*64+i];
    g_WvT[i*64+c] = Wv[c*64+i];
    g_W2T[i*64+c] = W2[c*64+i]*s2;
    if (i < 8) {
        float sw = bnw1[i] * rsqrtf(bnw1[24+i] + 1e-5f);
        g_Ww1f[c*8+i] = Ww1[i*64+c]*sw;
    }
    if (i == 0) {
        g_t1[c] = bn1[64+c] - bn1[128+c]*s1;
        g_bqv[c] = bq[c]; g_bkv[c] = bk[c]; g_bvv[c] = bv[c];
        g_Wp2b[c*4+0] = Wp2[c*3+0];
        g_Wp2b[c*4+1] = Wp2[c*3+1];
        g_Wp2b[c*4+2] = Wp2[c*3+2];
        g_Wp2b[c*4+3] = bp2[c];
        float s0 = bnw0[c] * rsqrtf(bnw0[192+c] + 1e-5f);
        g_s0t0[c*2+0] = s0;
        g_s0t0[c*2+1] = bnw0[64+c] - bnw0[128+c]*s0;
        float sm = bn_mid[c] * rsqrtf(bn_mid[192+c] + 1e-5f);
        g_smt[c*2+0] = sm;
        g_smt[c*2+1] = bn_mid[64+c] - bn_mid[128+c]*sm;
        g_t2[c] = bn2[64+c] - bn2[128+c]*s2;
    }
    if (c == 0) {
        if (i < 3) {
            float sp = bnp1[i] * rsqrtf(bnp1[9+i] + 1e-5f);
            g_Wp1f[i*3+0] = Wp1[i*3+0]*sp;
            g_Wp1f[i*3+1] = Wp1[i*3+1]*sp;
            g_Wp1f[i*3+2] = Wp1[i*3+2]*sp;
            g_tp[i] = bnp1[3+i] - bnp1[6+i]*sp;
        }
        if (i < 8) {
            float sw = bnw1[i] * rsqrtf(bnw1[24+i] + 1e-5f);
            g_tw1[i]  = bnw1[8+i] - bnw1[16+i]*sw;
            g_bw2v[i] = bw2[i];
        }
        g_Ww2m[i] = Ww2[i];
    }
}

// ---------------- f = relu(bn1(W1 x)), point-major --------------------------
__global__ void __launch_bounds__(256) k_featf(const float* __restrict__ feat)
{
    __shared__ float sfe[32*68];
    int t  = threadIdx.x;
    int b  = blockIdx.y;
    int n0 = blockIdx.x * 64;

    #pragma unroll
    for (int r = 0; r < 8; r++) {
        int li = r*256 + t;
        int i = li >> 6, p = li & 63;
        sfe[i*68+p] = feat[(size_t)(b*32 + i)*NPT + n0 + p];
    }
    __syncthreads();

    int cc = t & 15, pg = t >> 4;
    int cb = 4*cc, pb = 4*pg;

    float af[4][4];
    #pragma unroll
    for (int a = 0; a < 4; a++)
        #pragma unroll
        for (int bj = 0; bj < 4; bj++) af[a][bj] = 0.f;

    #pragma unroll
    for (int i = 0; i < 32; i++) {
        float4 w  = *(const float4*)&g_W1f[i*64 + cb];
        float4 fv = *(const float4*)&sfe[i*68 + pb];
        float wc[4] = {w.x,w.y,w.z,w.w};
        float fp[4] = {fv.x,fv.y,fv.z,fv.w};
        #pragma unroll
        for (int ch = 0; ch < 4; ch++)
            #pragma unroll
            for (int pp = 0; pp < 4; pp++)
                af[ch][pp] = fmaf(wc[ch], fp[pp], af[ch][pp]);
    }
    float4 t1v = *(const float4*)&g_t1[cb];
    float tb[4] = {t1v.x, t1v.y, t1v.z, t1v.w};
    #pragma unroll
    for (int ch = 0; ch < 4; ch++)
        #pragma unroll
        for (int pp = 0; pp < 4; pp++)
            af[ch][pp] = fmaxf(af[ch][pp] + tb[ch], 0.f);

    size_t fb = ((size_t)b*NPT + n0) * 64;
    #pragma unroll
    for (int pp = 0; pp < 4; pp++)
        *(float4*)&g_f[fb + (size_t)(pb+pp)*64 + cb] =
            make_float4(af[0][pp], af[1][pp], af[2][pp], af[3][pp]);
}

// ---------------- q/k/v projection with pr/bnw0 folding ---------------------
// z=0 -> QS = s0*(Wq f + bq) - t0       (g_q, stride 64)
// z=1 -> K' = s0*(Wk f + bk + pr)       (g_kv k-half, stride 128)
// z=2 -> V' = Wv f + bv + pr            (g_kv v-half, stride 128)
__global__ void __launch_bounds__(256) k_qkv(const float* __restrict__ xyz)
{
    __shared__ float sf[64*68];
    __shared__ float sh[64*4];   // pos-MLP hidden per point
    int t  = threadIdx.x;
    int b  = blockIdx.y;
    int n0 = blockIdx.x * 64;
    int z  = blockIdx.z;
    const float* W    = (z == 0) ? g_WqT : (z == 1) ? g_WkT : g_WvT;
    const float* bias = (z == 0) ? g_bqv : (z == 1) ? g_bkv : g_bvv;
    float*       dst  = (z == 0) ? g_q   : (z == 1) ? g_kv  : (g_kv + 64);
    int          dstr = (z == 0) ? 64 : 128;

    size_t fb = ((size_t)b*NPT + n0) * 64;

    // stage f tile transposed: sf[c][p]
    int p = t & 63, chunk = t >> 6;
    #pragma unroll
    for (int j = 0; j < 4; j++) {
        int ch = chunk*16 + 4*j;
        float4 v = *(const float4*)&g_f[fb + (size_t)p*64 + ch];
        sf[(ch+0)*68+p] = v.x;
        sf[(ch+1)*68+p] = v.y;
        sf[(ch+2)*68+p] = v.z;
        sf[(ch+3)*68+p] = v.w;
    }
    if (z != 0 && t < 64) {
        const float* xr = xyz + ((size_t)b*NPT + n0 + t)*3;
        float X = xr[0], Y = xr[1], Z = xr[2];
        sh[t*4+0] = fmaxf(fmaf(g_Wp1f[0], X, fmaf(g_Wp1f[1], Y, fmaf(g_Wp1f[2], Z, g_tp[0]))), 0.f);
        sh[t*4+1] = fmaxf(fmaf(g_Wp1f[3], X, fmaf(g_Wp1f[4], Y, fmaf(g_Wp1f[5], Z, g_tp[1]))), 0.f);
        sh[t*4+2] = fmaxf(fmaf(g_Wp1f[6], X, fmaf(g_Wp1f[7], Y, fmaf(g_Wp1f[8], Z, g_tp[2]))), 0.f);
    }
    __syncthreads();

    int cc = t & 15, pg = t >> 4;
    int cb = 4*cc, pb = 4*pg;

    float a[4][4];
    #pragma unroll
    for (int x = 0; x < 4; x++)
        #pragma unroll
        for (int y = 0; y < 4; y++) a[x][y] = 0.f;

    #pragma unroll 8
    for (int c = 0; c < 64; c++) {
        float4 w  = *(const float4*)&W[c*64 + cb];
        float4 fv = *(const float4*)&sf[c*68 + pb];
        float wc[4] = {w.x,w.y,w.z,w.w};
        float fp[4] = {fv.x,fv.y,fv.z,fv.w};
        #pragma unroll
        for (int ch = 0; ch < 4; ch++)
            #pragma unroll
            for (int pp = 0; pp < 4; pp++)
                a[ch][pp] = fmaf(wc[ch], fp[pp], a[ch][pp]);
    }
    float4 bb = *(const float4*)&bias[cb];
    float bvr[4] = {bb.x, bb.y, bb.z, bb.w};

    if (z == 0) {
        #pragma unroll
        for (int pp = 0; pp < 4; pp++) {
            float o[4];
            #pragma unroll
            for (int ch = 0; ch < 4; ch++) {
                float2 st = *(const float2*)&g_s0t0[(cb+ch)*2];
                o[ch] = fmaf(st.x, a[ch][pp] + bvr[ch], -st.y);
            }
            *(float4*)&dst[((size_t)b*NPT + n0 + pb + pp)*64 + cb] =
                make_float4(o[0], o[1], o[2], o[3]);
        }
    } else {
        #pragma unroll
        for (int pp = 0; pp < 4; pp++) {
            float h0 = sh[(pb+pp)*4+0], h1 = sh[(pb+pp)*4+1], h2 = sh[(pb+pp)*4+2];
            float o[4];
            #pragma unroll
            for (int ch = 0; ch < 4; ch++) {
                float4 wp = *(const float4*)&g_Wp2b[(cb+ch)*4];
                float pr = fmaf(wp.x, h0, fmaf(wp.y, h1, fmaf(wp.z, h2, wp.w)));
                float val = a[ch][pp] + bvr[ch] + pr;
                if (z == 1) val *= g_s0t0[(cb+ch)*2];
                o[ch] = val;
            }
            *(float4*)&dst[((size_t)b*NPT + n0 + pb + pp)*128 + cb] =
                make_float4(o[0], o[1], o[2], o[3]);
        }
    }
}

__device__ __forceinline__ float lrelu(float x) { return fmaxf(x, 0.2f*x); }

// ---------------- attention + aggregation + output --------------------------
// One warp per point. Phase1: lane=(k,h). Phase3: lane=channel pair.
#define WPB 4
__global__ void __launch_bounds__(128) k_attn(const int* __restrict__ nidx,
                                              float*     __restrict__ out)
{
    __shared__ float skv[WPB][16*128];  // 32 KB: per-warp 16 rows x 512B, swizzled
    __shared__ float swt[WPB][132];
    __shared__ float sxm[WPB][64];
    __shared__ float sout[WPB*64];
    __shared__ float sWw1f[512];
    __shared__ float sWw2[64];
    __shared__ float sAux[16];   // [0:8) tw1, [8:16) bw2

    int t = threadIdx.x;
    sWw1f[t]       = g_Ww1f[t];
    sWw1f[128+t]   = g_Ww1f[128+t];
    sWw1f[256+t]   = g_Ww1f[256+t];
    sWw1f[384+t]   = g_Ww1f[384+t];
    if (t < 64)    sWw2[t] = g_Ww2m[t];
    if (t < 8)   { sAux[t] = g_tw1[t]; sAux[8+t] = g_bw2v[t]; }
    __syncthreads();

    int warp = t >> 5, l = t & 31;
    int pid = blockIdx.x * WPB + warp;
    int b   = pid >> 14;
    int n   = pid & 16383;
    size_t rowb  = (size_t)b * NPT;
    size_t pbase = (rowb + n) * 64;

    int k = l & 15, h = l >> 4;
    int c0 = 32 * h;

    const int* nrow = nidx + (size_t)pid*16;
    int myidx = (l < 16) ? __ldg(nrow + l) : 0;

    // cooperative gather: one full 512B K'|V' row per instruction, swizzled STS
    float* skvw = skv[warp];
    #pragma unroll
    for (int i = 0; i < 16; i++) {
        int r = __shfl_sync(0xffffffffu, myidx, i);
        float4 val = __ldg((const float4*)(g_kv + (rowb + r)*128) + l);
        int pp = l ^ (i & 7);
        *(float4*)&skvw[i*128 + pp*4] = val;
    }
    __syncwarp();

    // phase 1: u = lrelu(K' - QS), accumulate Ww1 partials over own 32 channels
    float w1p[8];
    #pragma unroll
    for (int j = 0; j < 8; j++) w1p[j] = 0.f;

    int sw8 = k & 7;
    #pragma unroll
    for (int s = 0; s < 8; s++) {
        int c = c0 + 4*s;
        float4 kk = *(const float4*)&skvw[k*128 + ((h*8 + s) ^ sw8)*4];
        float4 qs = __ldg((const float4*)(g_q + pbase + c));
        float kr[4] = {kk.x,kk.y,kk.z,kk.w};
        float qr[4] = {qs.x,qs.y,qs.z,qs.w};
        #pragma unroll
        for (int e = 0; e < 4; e++) {
            int ch = c + e;
            float u = lrelu(kr[e] - qr[e]);
            float4 wA = *(const float4*)(sWw1f + ch*8);
            float4 wB = *(const float4*)(sWw1f + ch*8 + 4);
            w1p[0] = fmaf(wA.x, u, w1p[0]); w1p[1] = fmaf(wA.y, u, w1p[1]);
            w1p[2] = fmaf(wA.z, u, w1p[2]); w1p[3] = fmaf(wA.w, u, w1p[3]);
            w1p[4] = fmaf(wB.x, u, w1p[4]); w1p[5] = fmaf(wB.y, u, w1p[5]);
            w1p[6] = fmaf(wB.z, u, w1p[6]); w1p[7] = fmaf(wB.w, u, w1p[7]);
        }
    }

    // combine the two channel halves
    #pragma unroll
    for (int j = 0; j < 8; j++)
        w1p[j] += __shfl_xor_sync(0xffffffffu, w1p[j], 16);

    float w1v[8];
    #pragma unroll
    for (int j = 0; j < 8; j++) w1v[j] = fmaxf(w1p[j] + sAux[j], 0.f);

    // each h-half computes 4 of the 8 Ww2 outputs
    float wt[4];
    #pragma unroll
    for (int jj = 0; jj < 4; jj++) {
        int j = 4*h + jj;
        float a = sAux[8+j];
        #pragma unroll
        for (int i = 0; i < 8; i++) a = fmaf(sWw2[j*8+i], w1v[i], a);
        wt[jj] = a;
    }
    *(float4*)&swt[warp][k*8 + 4*h] = make_float4(wt[0], wt[1], wt[2], wt[3]);
    __syncwarp();

    // softmax over K: lane handles j = l>>2, k in [4*(l&3), +4)
    {
        int j = l >> 2, kq = l & 3;
        float v0 = swt[warp][(4*kq+0)*8 + j];
        float v1 = swt[warp][(4*kq+1)*8 + j];
        float v2 = swt[warp][(4*kq+2)*8 + j];
        float v3 = swt[warp][(4*kq+3)*8 + j];
        float mx = fmaxf(fmaxf(v0, v1), fmaxf(v2, v3));
        mx = fmaxf(mx, __shfl_xor_sync(0xffffffffu, mx, 1));
        mx = fmaxf(mx, __shfl_xor_sync(0xffffffffu, mx, 2));
        float e0 = __expf(v0 - mx), e1 = __expf(v1 - mx);
        float e2 = __expf(v2 - mx), e3 = __expf(v3 - mx);
        float sm = e0 + e1 + e2 + e3;
        sm += __shfl_xor_sync(0xffffffffu, sm, 1);
        sm += __shfl_xor_sync(0xffffffffu, sm, 2);
        float inv = __fdividef(1.f, sm);
        swt[warp][(4*kq+0)*8 + j] = e0 * inv;
        swt[warp][(4*kq+1)*8 + j] = e1 * inv;
        swt[warp][(4*kq+2)*8 + j] = e2 * inv;
        swt[warp][(4*kq+3)*8 + j] = e3 * inv;
    }
    __syncwarp();

    // phase 3: lane owns channels 2l, 2l+1; weighted sum of V' over 16 neighbors
    int cc0 = 2*l;
    int j0 = cc0 & 7;                 // weight dim = channel % 8
    int chunkv = 16 + (l >> 1);       // 16B-chunk of V'[cc0] within a row
    float acc0 = 0.f, acc1 = 0.f;
    #pragma unroll
    for (int kk2 = 0; kk2 < 16; kk2++) {
        float2 wv = *(const float2*)&swt[warp][kk2*8 + j0];
        int pos = chunkv ^ (kk2 & 7);
        float2 vv = *(const float2*)&skvw[kk2*128 + pos*4 + (cc0 & 3)];
        acc0 = fmaf(wv.x, vv.x, acc0);
        acc1 = fmaf(wv.y, vv.y, acc1);
    }

    // bn_mid + lrelu
    float4 sm4 = *(const float4*)(g_smt + 4*l);
    float xa = lrelu(fmaf(sm4.x, acc0, sm4.y));
    float xb = lrelu(fmaf(sm4.z, acc1, sm4.w));
    *(float2*)&sxm[warp][cc0] = make_float2(xa, xb);
    __syncwarp();

    // conv2 (BN folded) + residual + lrelu
    float2 t2v = *(const float2*)(g_t2 + cc0);
    float o0 = t2v.x, o1 = t2v.y;
    #pragma unroll 4
    for (int c4 = 0; c4 < 64; c4 += 4) {
        float4 xv = *(const float4*)&sxm[warp][c4];
        float2 wa = *(const float2*)(g_W2T + (c4+0)*64 + cc0);
        float2 wb = *(const float2*)(g_W2T + (c4+1)*64 + cc0);
        float2 wc = *(const float2*)(g_W2T + (c4+2)*64 + cc0);
        float2 wd = *(const float2*)(g_W2T + (c4+3)*64 + cc0);
        o0 = fmaf(wa.x, xv.x, o0); o1 = fmaf(wa.y, xv.x, o1);
        o0 = fmaf(wb.x, xv.y, o0); o1 = fmaf(wb.y, xv.y, o1);
        o0 = fmaf(wc.x, xv.z, o0); o1 = fmaf(wc.y, xv.z, o1);
        o0 = fmaf(wd.x, xv.w, o0); o1 = fmaf(wd.y, xv.w, o1);
    }
    float2 fres = *(const float2*)(g_f + pbase + cc0);
    o0 = lrelu(o0 + fres.x);
    o1 = lrelu(o1 + fres.y);
    sout[(cc0)*WPB + warp]   = o0;
    sout[(cc0+1)*WPB + warp] = o1;
    __syncthreads();

    // coalesced channel-major output (WPB=4 points per block, aligned in n)
    int flat = t * 2;
    int c = flat >> 2, p = flat & 3;
    int bB = (blockIdx.x * WPB) >> 14;
    int n0 = (blockIdx.x * WPB) & 16383;
    float2 val = *(float2*)&sout[flat];
    *(float2*)&out[((size_t)(bB*64 + c))*NPT + n0 + p] = val;
}

extern "C" void kernel_launch(void* const* d_in, const int* in_sizes, int n_in,
                              void* d_out, int out_size)
{
    const float* feature = (const float*)d_in[0];
    const float* xyz     = (const float*)d_in[1];
    const float* W1      = (const float*)d_in[2];
    const float* bn1     = (const float*)d_in[3];
    const float* Wq      = (const float*)d_in[4];
    const float* bq      = (const float*)d_in[5];
    const float* Wk      = (const float*)d_in[6];
    const float* bk      = (const float*)d_in[7];
    const float* Wv      = (const float*)d_in[8];
    const float* bv      = (const float*)d_in[9];
    const float* Wp1     = (const float*)d_in[10];
    const float* bnp1    = (const float*)d_in[11];
    const float* Wp2     = (const float*)d_in[12];
    const float* bp2     = (const float*)d_in[13];
    const float* bnw0    = (const float*)d_in[14];
    const float* Ww1     = (const float*)d_in[15];
    const float* bnw1    = (const float*)d_in[16];
    const float* Ww2     = (const float*)d_in[17];
    const float* bw2     = (const float*)d_in[18];
    const float* bn_mid  = (const float*)d_in[19];
    const float* W2      = (const float*)d_in[20];
    const float* bn2     = (const float*)d_in[21];
    const int*   nidx    = (const int*)d_in[22];
    float* out = (float*)d_out;

    k_prep<<<64, 64>>>(W1, bn1, Wq, bq, Wk, bk, Wv, bv, Wp1, bnp1, Wp2, bp2,
                       bnw0, Ww1, bnw1, Ww2, bw2, bn_mid, W2, bn2);
    dim3 gf(NPT/64, BB);
    k_featf<<<gf, 256>>>(feature);
    dim3 gq(NPT/64, BB, 3);
    k_qkv<<<gq, 256>>>(xyz);
    k_attn<<<(BB*NPT)/WPB, 128>>>(nidx, out);
}

// round 7
// speedup vs baseline: 1.9286x; 1.1324x over previous
#include <cuda_runtime.h>

#define NPT 16384
#define BB  2

__device__ float g_f [BB*NPT*64];
__device__ float g_q [BB*NPT*64];     // QS = s0*q - t0
__device__ float g_kv[BB*NPT*128];    // [row][0:64]=s0*(k+pr), [64:128]=v+pr
__device__ float g_xm[BB*NPT*64];     // bn_mid/lrelu output, point-major

__device__ float g_W1f[32*64];
__device__ float g_t1[64];
__device__ float g_WqT[64*64], g_WkT[64*64], g_WvT[64*64];
__device__ float g_bqv[64], g_bkv[64], g_bvv[64];
__device__ float g_Wp1f[9], g_tp[3];
__device__ float g_Wp2b[64*4];
__device__ float g_s0t0[64*2];
__device__ float g_Ww1f[64*8];
__device__ float g_tw1[8], g_Ww2m[64], g_bw2v[8];
__device__ float g_smt[64*2];
__device__ float g_W2T[64*64], g_t2[64];

// ---------------- prep: 64 blocks x 64 threads ------------------------------
__global__ void k_prep(const float* __restrict__ W1,  const float* __restrict__ bn1,
                       const float* __restrict__ Wq,  const float* __restrict__ bq,
                       const float* __restrict__ Wk,  const float* __restrict__ bk,
                       const float* __restrict__ Wv,  const float* __restrict__ bv,
                       const float* __restrict__ Wp1, const float* __restrict__ bnp1,
                       const float* __restrict__ Wp2, const float* __restrict__ bp2,
                       const float* __restrict__ bnw0,const float* __restrict__ Ww1,
                       const float* __restrict__ bnw1,const float* __restrict__ Ww2,
                       const float* __restrict__ bw2, const float* __restrict__ bn_mid,
                       const float* __restrict__ W2,  const float* __restrict__ bn2)
{
    int c = blockIdx.x;   // 0..63 output channel
    int i = threadIdx.x;  // 0..63 input channel
    float s1 = bn1[c] * rsqrtf(bn1[192+c] + 1e-5f);
    float s2 = bn2[c] * rsqrtf(bn2[192+c] + 1e-5f);
    if (i < 32) g_W1f[i*64+c] = W1[c*32+i]*s1;
    g_WqT[i*64+c] = Wq[c*64+i];
    g_WkT[i*64+c] = Wk[c*64+i];
    g_WvT[i*64+c] = Wv[c*64+i];
    g_W2T[i*64+c] = W2[c*64+i]*s2;
    if (i < 8) {
        float sw = bnw1[i] * rsqrtf(bnw1[24+i] + 1e-5f);
        g_Ww1f[c*8+i] = Ww1[i*64+c]*sw;
    }
    if (i == 0) {
        g_t1[c] = bn1[64+c] - bn1[128+c]*s1;
        g_bqv[c] = bq[c]; g_bkv[c] = bk[c]; g_bvv[c] = bv[c];
        g_Wp2b[c*4+0] = Wp2[c*3+0];
        g_Wp2b[c*4+1] = Wp2[c*3+1];
        g_Wp2b[c*4+2] = Wp2[c*3+2];
        g_Wp2b[c*4+3] = bp2[c];
        float s0 = bnw0[c] * rsqrtf(bnw0[192+c] + 1e-5f);
        g_s0t0[c*2+0] = s0;
        g_s0t0[c*2+1] = bnw0[64+c] - bnw0[128+c]*s0;
        float sm = bn_mid[c] * rsqrtf(bn_mid[192+c] + 1e-5f);
        g_smt[c*2+0] = sm;
        g_smt[c*2+1] = bn_mid[64+c] - bn_mid[128+c]*sm;
        g_t2[c] = bn2[64+c] - bn2[128+c]*s2;
    }
    if (c == 0) {
        if (i < 3) {
            float sp = bnp1[i] * rsqrtf(bnp1[9+i] + 1e-5f);
            g_Wp1f[i*3+0] = Wp1[i*3+0]*sp;
            g_Wp1f[i*3+1] = Wp1[i*3+1]*sp;
            g_Wp1f[i*3+2] = Wp1[i*3+2]*sp;
            g_tp[i] = bnp1[3+i] - bnp1[6+i]*sp;
        }
        if (i < 8) {
            float sw = bnw1[i] * rsqrtf(bnw1[24+i] + 1e-5f);
            g_tw1[i]  = bnw1[8+i] - bnw1[16+i]*sw;
            g_bw2v[i] = bw2[i];
        }
        g_Ww2m[i] = Ww2[i];
    }
}

// ---------------- f = relu(bn1(W1 x)), point-major --------------------------
__global__ void __launch_bounds__(256) k_featf(const float* __restrict__ feat)
{
    __shared__ float sfe[32*68];
    int t  = threadIdx.x;
    int b  = blockIdx.y;
    int n0 = blockIdx.x * 64;

    #pragma unroll
    for (int r = 0; r < 8; r++) {
        int li = r*256 + t;
        int i = li >> 6, p = li & 63;
        sfe[i*68+p] = feat[(size_t)(b*32 + i)*NPT + n0 + p];
    }
    __syncthreads();

    int cc = t & 15, pg = t >> 4;
    int cb = 4*cc, pb = 4*pg;

    float af[4][4];
    #pragma unroll
    for (int a = 0; a < 4; a++)
        #pragma unroll
        for (int bj = 0; bj < 4; bj++) af[a][bj] = 0.f;

    #pragma unroll
    for (int i = 0; i < 32; i++) {
        float4 w  = *(const float4*)&g_W1f[i*64 + cb];
        float4 fv = *(const float4*)&sfe[i*68 + pb];
        float wc[4] = {w.x,w.y,w.z,w.w};
        float fp[4] = {fv.x,fv.y,fv.z,fv.w};
        #pragma unroll
        for (int ch = 0; ch < 4; ch++)
            #pragma unroll
            for (int pp = 0; pp < 4; pp++)
                af[ch][pp] = fmaf(wc[ch], fp[pp], af[ch][pp]);
    }
    float4 t1v = *(const float4*)&g_t1[cb];
    float tb[4] = {t1v.x, t1v.y, t1v.z, t1v.w};
    #pragma unroll
    for (int ch = 0; ch < 4; ch++)
        #pragma unroll
        for (int pp = 0; pp < 4; pp++)
            af[ch][pp] = fmaxf(af[ch][pp] + tb[ch], 0.f);

    size_t fb = ((size_t)b*NPT + n0) * 64;
    #pragma unroll
    for (int pp = 0; pp < 4; pp++)
        *(float4*)&g_f[fb + (size_t)(pb+pp)*64 + cb] =
            make_float4(af[0][pp], af[1][pp], af[2][pp], af[3][pp]);
}

// ---------------- q/k/v projection with pr/bnw0 folding ---------------------
__global__ void __launch_bounds__(256) k_qkv(const float* __restrict__ xyz)
{
    __shared__ float sf[64*68];
    __shared__ float sh[64*4];
    int t  = threadIdx.x;
    int b  = blockIdx.y;
    int n0 = blockIdx.x * 64;
    int z  = blockIdx.z;
    const float* W    = (z == 0) ? g_WqT : (z == 1) ? g_WkT : g_WvT;
    const float* bias = (z == 0) ? g_bqv : (z == 1) ? g_bkv : g_bvv;
    float*       dst  = (z == 0) ? g_q   : (z == 1) ? g_kv  : (g_kv + 64);

    size_t fb = ((size_t)b*NPT + n0) * 64;

    int p = t & 63, chunk = t >> 6;
    #pragma unroll
    for (int j = 0; j < 4; j++) {
        int ch = chunk*16 + 4*j;
        float4 v = *(const float4*)&g_f[fb + (size_t)p*64 + ch];
        sf[(ch+0)*68+p] = v.x;
        sf[(ch+1)*68+p] = v.y;
        sf[(ch+2)*68+p] = v.z;
        sf[(ch+3)*68+p] = v.w;
    }
    if (z != 0 && t < 64) {
        const float* xr = xyz + ((size_t)b*NPT + n0 + t)*3;
        float X = xr[0], Y = xr[1], Z = xr[2];
        sh[t*4+0] = fmaxf(fmaf(g_Wp1f[0], X, fmaf(g_Wp1f[1], Y, fmaf(g_Wp1f[2], Z, g_tp[0]))), 0.f);
        sh[t*4+1] = fmaxf(fmaf(g_Wp1f[3], X, fmaf(g_Wp1f[4], Y, fmaf(g_Wp1f[5], Z, g_tp[1]))), 0.f);
        sh[t*4+2] = fmaxf(fmaf(g_Wp1f[6], X, fmaf(g_Wp1f[7], Y, fmaf(g_Wp1f[8], Z, g_tp[2]))), 0.f);
    }
    __syncthreads();

    int cc = t & 15, pg = t >> 4;
    int cb = 4*cc, pb = 4*pg;

    float a[4][4];
    #pragma unroll
    for (int x = 0; x < 4; x++)
        #pragma unroll
        for (int y = 0; y < 4; y++) a[x][y] = 0.f;

    #pragma unroll 8
    for (int c = 0; c < 64; c++) {
        float4 w  = *(const float4*)&W[c*64 + cb];
        float4 fv = *(const float4*)&sf[c*68 + pb];
        float wc[4] = {w.x,w.y,w.z,w.w};
        float fp[4] = {fv.x,fv.y,fv.z,fv.w};
        #pragma unroll
        for (int ch = 0; ch < 4; ch++)
            #pragma unroll
            for (int pp = 0; pp < 4; pp++)
                a[ch][pp] = fmaf(wc[ch], fp[pp], a[ch][pp]);
    }
    float4 bb = *(const float4*)&bias[cb];
    float bvr[4] = {bb.x, bb.y, bb.z, bb.w};

    if (z == 0) {
        #pragma unroll
        for (int pp = 0; pp < 4; pp++) {
            float o[4];
            #pragma unroll
            for (int ch = 0; ch < 4; ch++) {
                float2 st = *(const float2*)&g_s0t0[(cb+ch)*2];
                o[ch] = fmaf(st.x, a[ch][pp] + bvr[ch], -st.y);
            }
            *(float4*)&dst[((size_t)b*NPT + n0 + pb + pp)*64 + cb] =
                make_float4(o[0], o[1], o[2], o[3]);
        }
    } else {
        #pragma unroll
        for (int pp = 0; pp < 4; pp++) {
            float h0 = sh[(pb+pp)*4+0], h1 = sh[(pb+pp)*4+1], h2 = sh[(pb+pp)*4+2];
            float o[4];
            #pragma unroll
            for (int ch = 0; ch < 4; ch++) {
                float4 wp = *(const float4*)&g_Wp2b[(cb+ch)*4];
                float pr = fmaf(wp.x, h0, fmaf(wp.y, h1, fmaf(wp.z, h2, wp.w)));
                float val = a[ch][pp] + bvr[ch] + pr;
                if (z == 1) val *= g_s0t0[(cb+ch)*2];
                o[ch] = val;
            }
            *(float4*)&dst[((size_t)b*NPT + n0 + pb + pp)*128 + cb] =
                make_float4(o[0], o[1], o[2], o[3]);
        }
    }
}

__device__ __forceinline__ float lrelu(float x) { return fmaxf(x, 0.2f*x); }

// ---------------- attention core: writes xm (point-major) -------------------
#define WPB 4
__global__ void __launch_bounds__(128) k_attn(const int* __restrict__ nidx)
{
    __shared__ float skv[WPB][16*64];   // K' only: 16 rows x 256B, swizzled
    __shared__ float swt[WPB][132];
    __shared__ float sWw1f[512];
    __shared__ float sWw2[64];
    __shared__ float sAux[16];

    int t = threadIdx.x;
    sWw1f[t]       = g_Ww1f[t];
    sWw1f[128+t]   = g_Ww1f[128+t];
    sWw1f[256+t]   = g_Ww1f[256+t];
    sWw1f[384+t]   = g_Ww1f[384+t];
    if (t < 64)    sWw2[t] = g_Ww2m[t];
    if (t < 8)   { sAux[t] = g_tw1[t]; sAux[8+t] = g_bw2v[t]; }
    __syncthreads();

    int warp = t >> 5, l = t & 31;
    int pid = blockIdx.x * WPB + warp;
    int b   = pid >> 14;
    int n   = pid & 16383;
    size_t rowb  = (size_t)b * NPT;
    size_t pbase = (rowb + n) * 64;

    int k = l & 15, h = l >> 4;
    int c0 = 32 * h;

    const int* nrow = nidx + (size_t)pid*16;
    int myidx = (l < 16) ? __ldg(nrow + l) : 0;

    // cooperative gather of K' (two rows per instruction), swizzled STS
    float* skvw = skv[warp];
    int i2 = l >> 4, ch16 = l & 15;
    #pragma unroll
    for (int i = 0; i < 8; i++) {
        int row = 2*i + i2;
        int r = __shfl_sync(0xffffffffu, myidx, row);
        float4 val = __ldg((const float4*)(g_kv + (rowb + r)*128) + ch16);
        int pp = ch16 ^ (row & 7);
        *(float4*)&skvw[row*64 + pp*4] = val;
    }
    __syncwarp();

    // phase 1: u = lrelu(K' - QS), accumulate Ww1 partials over own 32 channels
    float w1p[8];
    #pragma unroll
    for (int j = 0; j < 8; j++) w1p[j] = 0.f;

    int sw8 = k & 7;
    #pragma unroll
    for (int s = 0; s < 8; s++) {
        int c = c0 + 4*s;
        float4 kk = *(const float4*)&skvw[k*64 + ((h*8 + s) ^ sw8)*4];
        float4 qs = __ldg((const float4*)(g_q + pbase + c));
        float kr[4] = {kk.x,kk.y,kk.z,kk.w};
        float qr[4] = {qs.x,qs.y,qs.z,qs.w};
        #pragma unroll
        for (int e = 0; e < 4; e++) {
            int ch = c + e;
            float u = lrelu(kr[e] - qr[e]);
            float4 wA = *(const float4*)(sWw1f + ch*8);
            float4 wB = *(const float4*)(sWw1f + ch*8 + 4);
            w1p[0] = fmaf(wA.x, u, w1p[0]); w1p[1] = fmaf(wA.y, u, w1p[1]);
            w1p[2] = fmaf(wA.z, u, w1p[2]); w1p[3] = fmaf(wA.w, u, w1p[3]);
            w1p[4] = fmaf(wB.x, u, w1p[4]); w1p[5] = fmaf(wB.y, u, w1p[5]);
            w1p[6] = fmaf(wB.z, u, w1p[6]); w1p[7] = fmaf(wB.w, u, w1p[7]);
        }
    }

    #pragma unroll
    for (int j = 0; j < 8; j++)
        w1p[j] += __shfl_xor_sync(0xffffffffu, w1p[j], 16);

    float w1v[8];
    #pragma unroll
    for (int j = 0; j < 8; j++) w1v[j] = fmaxf(w1p[j] + sAux[j], 0.f);

    float wt[4];
    #pragma unroll
    for (int jj = 0; jj < 4; jj++) {
        int j = 4*h + jj;
        float a = sAux[8+j];
        #pragma unroll
        for (int i = 0; i < 8; i++) a = fmaf(sWw2[j*8+i], w1v[i], a);
        wt[jj] = a;
    }
    *(float4*)&swt[warp][k*8 + 4*h] = make_float4(wt[0], wt[1], wt[2], wt[3]);
    __syncwarp();

    // softmax over K
    {
        int j = l >> 2, kq = l & 3;
        float v0 = swt[warp][(4*kq+0)*8 + j];
        float v1 = swt[warp][(4*kq+1)*8 + j];
        float v2 = swt[warp][(4*kq+2)*8 + j];
        float v3 = swt[warp][(4*kq+3)*8 + j];
        float mx = fmaxf(fmaxf(v0, v1), fmaxf(v2, v3));
        mx = fmaxf(mx, __shfl_xor_sync(0xffffffffu, mx, 1));
        mx = fmaxf(mx, __shfl_xor_sync(0xffffffffu, mx, 2));
        float e0 = __expf(v0 - mx), e1 = __expf(v1 - mx);
        float e2 = __expf(v2 - mx), e3 = __expf(v3 - mx);
        float sm = e0 + e1 + e2 + e3;
        sm += __shfl_xor_sync(0xffffffffu, sm, 1);
        sm += __shfl_xor_sync(0xffffffffu, sm, 2);
        float inv = __fdividef(1.f, sm);
        swt[warp][(4*kq+0)*8 + j] = e0 * inv;
        swt[warp][(4*kq+1)*8 + j] = e1 * inv;
        swt[warp][(4*kq+2)*8 + j] = e2 * inv;
        swt[warp][(4*kq+3)*8 + j] = e3 * inv;
    }
    __syncwarp();

    // phase 3: lane owns channels 2l, 2l+1; V' read from global (L2-hot)
    int cc0 = 2*l;
    int j0 = cc0 & 7;
    float acc0 = 0.f, acc1 = 0.f;
    #pragma unroll
    for (int kk2 = 0; kk2 < 16; kk2++) {
        float2 wv = *(const float2*)&swt[warp][kk2*8 + j0];
        int r = __shfl_sync(0xffffffffu, myidx, kk2);
        float2 vv = __ldg((const float2*)(g_kv + (rowb + r)*128 + 64 + cc0));
        acc0 = fmaf(wv.x, vv.x, acc0);
        acc1 = fmaf(wv.y, vv.y, acc1);
    }

    // bn_mid + lrelu, write xm point-major
    float4 sm4 = *(const float4*)(g_smt + 4*l);
    float xa = lrelu(fmaf(sm4.x, acc0, sm4.y));
    float xb = lrelu(fmaf(sm4.z, acc1, sm4.w));
    *(float2*)&g_xm[pbase + cc0] = make_float2(xa, xb);
}

// ---------------- conv2 + residual + lrelu, tiled GEMM -----------------------
__global__ void __launch_bounds__(256) k_out(float* __restrict__ out)
{
    __shared__ float sbuf[64*68];
    int t  = threadIdx.x;
    int b  = blockIdx.y;
    int n0 = blockIdx.x * 64;
    size_t base = (size_t)b*NPT + n0;

    // stage xm transposed: sbuf[c][p]
    int p = t & 63, chunk = t >> 6;
    #pragma unroll
    for (int j = 0; j < 4; j++) {
        int ch = chunk*16 + 4*j;
        float4 v = *(const float4*)&g_xm[(base + p)*64 + ch];
        sbuf[(ch+0)*68+p] = v.x;
        sbuf[(ch+1)*68+p] = v.y;
        sbuf[(ch+2)*68+p] = v.z;
        sbuf[(ch+3)*68+p] = v.w;
    }
    __syncthreads();

    int cc = t & 15, pg = t >> 4;
    int cb = 4*cc, pb = 4*pg;

    float a[4][4];
    #pragma unroll
    for (int x = 0; x < 4; x++)
        #pragma unroll
        for (int y = 0; y < 4; y++) a[x][y] = 0.f;

    #pragma unroll 8
    for (int c = 0; c < 64; c++) {
        float4 w  = *(const float4*)&g_W2T[c*64 + cb];
        float4 xv = *(const float4*)&sbuf[c*68 + pb];
        float wc[4] = {w.x,w.y,w.z,w.w};
        float xp[4] = {xv.x,xv.y,xv.z,xv.w};
        #pragma unroll
        for (int ch = 0; ch < 4; ch++)
            #pragma unroll
            for (int pp = 0; pp < 4; pp++)
                a[ch][pp] = fmaf(wc[ch], xp[pp], a[ch][pp]);
    }
    __syncthreads();   // done reading sbuf, reuse as output stage

    float4 t2v = *(const float4*)&g_t2[cb];
    float tb[4] = {t2v.x, t2v.y, t2v.z, t2v.w};
    #pragma unroll
    for (int pp = 0; pp < 4; pp++) {
        float4 fv = *(const float4*)&g_f[(base + pb + pp)*64 + cb];
        float fr[4] = {fv.x, fv.y, fv.z, fv.w};
        #pragma unroll
        for (int ch = 0; ch < 4; ch++)
            sbuf[(cb+ch)*68 + pb + pp] = lrelu(a[ch][pp] + tb[ch] + fr[ch]);
    }
    __syncthreads();

    // coalesced channel-major store
    int cO = t >> 2, q = t & 3;
    #pragma unroll
    for (int i = 0; i < 4; i++) {
        float4 vq = *(const float4*)&sbuf[cO*68 + q*16 + 4*i];
        *(float4*)&out[((size_t)(b*64 + cO))*NPT + n0 + q*16 + 4*i] = vq;
    }
}

extern "C" void kernel_launch(void* const* d_in, const int* in_sizes, int n_in,
                              void* d_out, int out_size)
{
    const float* feature = (const float*)d_in[0];
    const float* xyz     = (const float*)d_in[1];
    const float* W1      = (const float*)d_in[2];
    const float* bn1     = (const float*)d_in[3];
    const float* Wq      = (const float*)d_in[4];
    const float* bq      = (const float*)d_in[5];
    const float* Wk      = (const float*)d_in[6];
    const float* bk      = (const float*)d_in[7];
    const float* Wv      = (const float*)d_in[8];
    const float* bv      = (const float*)d_in[9];
    const float* Wp1     = (const float*)d_in[10];
    const float* bnp1    = (const float*)d_in[11];
    const float* Wp2     = (const float*)d_in[12];
    const float* bp2     = (const float*)d_in[13];
    const float* bnw0    = (const float*)d_in[14];
    const float* Ww1     = (const float*)d_in[15];
    const float* bnw1    = (const float*)d_in[16];
    const float* Ww2     = (const float*)d_in[17];
    const float* bw2     = (const float*)d_in[18];
    const float* bn_mid  = (const float*)d_in[19];
    const float* W2      = (const float*)d_in[20];
    const float* bn2     = (const float*)d_in[21];
    const int*   nidx    = (const int*)d_in[22];
    float* out = (float*)d_out;

    k_prep<<<64, 64>>>(W1, bn1, Wq, bq, Wk, bk, Wv, bv, Wp1, bnp1, Wp2, bp2,
                       bnw0, Ww1, bnw1, Ww2, bw2, bn_mid, W2, bn2);
    dim3 gf(NPT/64, BB);
    k_featf<<<gf, 256>>>(feature);
    dim3 gq(NPT/64, BB, 3);
    k_qkv<<<gq, 256>>>(xyz);
    k_attn<<<(BB*NPT)/WPB, 128>>>(nidx);
    k_out<<<gf, 256>>>(out);
}